// round 2
// baseline (speedup 1.0000x reference)
#include <cuda_runtime.h>
#include <cstdint>

// ---------------------------------------------------------------------------
// MobileMQA: q/k/v conv1x1 -> (k,v) downsample branch (dw3x3 s2, GN+SiLU,
// pw1x1, GN+SiLU) -> multi-head attention (N=1024 queries vs M=256 kv).
// B=32, C=256, H=W=32, heads=8, Dh=32, groups=32 (8 ch/group).
// ---------------------------------------------------------------------------

#define BATCH 32
#define CH 256
#define HW 1024          // 32*32
#define HWD 256          // 16*16
#define NH 8
#define DH 32
#define GROUPS 32
#define CPG 8            // channels per group
#define EPS 1e-5f

// Single scratch arena (floats):
// q:      [0,        8388608)   (B,C,HW)
// kfull:  [8388608, 16777216)
// vfull:  [16777216,25165824)
// kds:    [25165824,27262976)   (B,C,HWD)
// vds:    [27262976,29360128)
// kbr:    [29360128,31457280)
// vbr:    [31457280,33554432)
__device__ float g_scratch[33554432];

#define OFF_Q     0
#define OFF_KFULL 8388608
#define OFF_VFULL 16777216
#define OFF_KDS   25165824
#define OFF_VDS   27262976
#define OFF_KBR   29360128
#define OFF_VBR   31457280

// ---------------------------------------------------------------------------
// Batched SGEMM: Y[b] = W (MxK) * X[b] (KxN) + bias, row-major.
// Tile 64x64, BK=16, 256 threads, 4x4 microtile per thread.
// M,N,K all multiples of 64/16 here (no bounds checks needed).
// ---------------------------------------------------------------------------
#define BM 64
#define BN 64
#define BK 16

__global__ void gemm_bias_kernel(const float* __restrict__ W,
                                 const float* __restrict__ X,
                                 const float* __restrict__ bias,
                                 float* __restrict__ Y,
                                 int M, int N, int K)
{
    const int b = blockIdx.z;
    const float* Xb = X + (size_t)b * K * N;
    float* Yb = Y + (size_t)b * M * N;

    __shared__ float sA[BK][BM + 1];   // A^T: sA[k][m], padded vs bank conflicts
    __shared__ float sB[BK][BN];

    const int t  = threadIdx.x;
    const int tx = t & 15;
    const int ty = t >> 4;
    const int row0 = blockIdx.y * BM + ty * 4;
    const int col0 = blockIdx.x * BN + tx * 4;

    float acc[4][4];
#pragma unroll
    for (int i = 0; i < 4; i++)
#pragma unroll
        for (int j = 0; j < 4; j++) acc[i][j] = 0.f;

    for (int k0 = 0; k0 < K; k0 += BK) {
        // load A tile: W[blockIdx.y*64 + m, k0 + k], 64*16 = 1024 elems
#pragma unroll
        for (int i = t; i < BM * BK; i += 256) {
            int m = i / BK, k = i % BK;
            sA[k][m] = W[(size_t)(blockIdx.y * BM + m) * K + k0 + k];
        }
        // load B tile: X[k0+k, blockIdx.x*64 + n], 16*64 elems (coalesced on n)
#pragma unroll
        for (int i = t; i < BK * BN; i += 256) {
            int k = i / BN, n = i % BN;
            sB[k][n] = Xb[(size_t)(k0 + k) * N + blockIdx.x * BN + n];
        }
        __syncthreads();

#pragma unroll
        for (int k = 0; k < BK; k++) {
            float a[4], bb[4];
#pragma unroll
            for (int i = 0; i < 4; i++) a[i]  = sA[k][ty * 4 + i];
#pragma unroll
            for (int j = 0; j < 4; j++) bb[j] = sB[k][tx * 4 + j];
#pragma unroll
            for (int i = 0; i < 4; i++)
#pragma unroll
                for (int j = 0; j < 4; j++) acc[i][j] += a[i] * bb[j];
        }
        __syncthreads();
    }

#pragma unroll
    for (int i = 0; i < 4; i++) {
        float bi = bias ? bias[row0 + i] : 0.f;
#pragma unroll
        for (int j = 0; j < 4; j++)
            Yb[(size_t)(row0 + i) * N + col0 + j] = acc[i][j] + bi;
    }
}

// ---------------------------------------------------------------------------
// Depthwise 3x3 stride-2 pad-1: (B,C,32,32) -> (B,C,16,16)
// ---------------------------------------------------------------------------
__global__ void dwconv_s2_kernel(const float* __restrict__ in,
                                 const float* __restrict__ w,
                                 float* __restrict__ out)
{
    int idx = blockIdx.x * blockDim.x + threadIdx.x;
    if (idx >= BATCH * CH * HWD) return;
    int ox = idx & 15;
    int oy = (idx >> 4) & 15;
    int c  = (idx >> 8) & 255;
    int b  = idx >> 16;

    const float* ib = in + ((size_t)b * CH + c) * HW;
    const float* wc = w + c * 9;
    float acc = 0.f;
#pragma unroll
    for (int ky = 0; ky < 3; ky++) {
        int iy = 2 * oy - 1 + ky;
        if ((unsigned)iy >= 32u) continue;
#pragma unroll
        for (int kx = 0; kx < 3; kx++) {
            int ix = 2 * ox - 1 + kx;
            if ((unsigned)ix >= 32u) continue;
            acc += ib[iy * 32 + ix] * wc[ky * 3 + kx];
        }
    }
    out[idx] = acc;
}

// ---------------------------------------------------------------------------
// GroupNorm (32 groups of 8 ch over 16x16 spatial) + SiLU, in-place.
// grid: (GROUPS, BATCH), 256 threads (one per pixel).
// ---------------------------------------------------------------------------
__global__ void gn_silu_kernel(float* __restrict__ x,
                               const float* __restrict__ scale,
                               const float* __restrict__ bias)
{
    const int g = blockIdx.x;
    const int b = blockIdx.y;
    float* base = x + ((size_t)b * CH + g * CPG) * HWD;
    const int p = threadIdx.x;

    float vals[CPG];
    float s = 0.f, s2 = 0.f;
#pragma unroll
    for (int c = 0; c < CPG; c++) {
        float v = base[c * HWD + p];
        vals[c] = v;
        s += v; s2 += v * v;
    }

    // block reduction (8 warps)
#pragma unroll
    for (int o = 16; o > 0; o >>= 1) {
        s  += __shfl_down_sync(0xffffffffu, s,  o);
        s2 += __shfl_down_sync(0xffffffffu, s2, o);
    }
    __shared__ float rs[8], rs2[8];
    __shared__ float mu_s, rstd_s;
    int warp = p >> 5, lane = p & 31;
    if (lane == 0) { rs[warp] = s; rs2[warp] = s2; }
    __syncthreads();
    if (p == 0) {
        float S = 0.f, S2 = 0.f;
#pragma unroll
        for (int w = 0; w < 8; w++) { S += rs[w]; S2 += rs2[w]; }
        float mu  = S * (1.f / (CPG * HWD));
        float var = S2 * (1.f / (CPG * HWD)) - mu * mu;
        mu_s = mu;
        rstd_s = rsqrtf(var + EPS);
    }
    __syncthreads();
    float mu = mu_s, rstd = rstd_s;

#pragma unroll
    for (int c = 0; c < CPG; c++) {
        int ch = g * CPG + c;
        float y = (vals[c] - mu) * rstd * scale[ch] + bias[ch];
        y = y / (1.f + __expf(-y));        // SiLU
        base[c * HWD + p] = y;
    }
}

// ---------------------------------------------------------------------------
// Attention: per (b, head): q (1024 x 32), k/v (256 x 32).
// Online-softmax; K/V tiled 128 rows at a time, stored [m][d] (stride 36 to
// dodge write conflicts; reads are all-lane broadcast float4 => FMA-bound).
// One thread per query row; 128 threads/block; grid (8, NH, B).
// ---------------------------------------------------------------------------
#define QT 128
#define MT 128
#define KPAD 36

__global__ void attn_kernel(const float* __restrict__ q,
                            const float* __restrict__ k,
                            const float* __restrict__ v,
                            float* __restrict__ out)
{
    __shared__ float sK[MT * KPAD];
    __shared__ float sV[MT * KPAD];

    const int b = blockIdx.z;
    const int h = blockIdx.y;
    const int r = blockIdx.x * QT + threadIdx.x;

    const float* qb = q + ((size_t)b * CH + h * DH) * HW;
    const float* kb = k + ((size_t)b * CH + h * DH) * HWD;
    const float* vb = v + ((size_t)b * CH + h * DH) * HWD;

    const float scale = 0.17677669529663687f;  // 1/sqrt(32)
    float qr[DH];
#pragma unroll
    for (int d = 0; d < DH; d++) qr[d] = qb[d * HW + r] * scale;

    float mx = -1e30f, sum = 0.f;
    float o[DH];
#pragma unroll
    for (int d = 0; d < DH; d++) o[d] = 0.f;

    for (int m0 = 0; m0 < HWD; m0 += MT) {
        __syncthreads();
        // load tile: 128 x 32 each; gmem coalesced on m, smem 4-way conflict ok
        for (int i = threadIdx.x; i < MT * DH; i += QT) {
            int d = i >> 7;          // i / MT
            int m = i & (MT - 1);
            sK[m * KPAD + d] = kb[d * HWD + m0 + m];
            sV[m * KPAD + d] = vb[d * HWD + m0 + m];
        }
        __syncthreads();

        for (int m = 0; m < MT; m++) {
            const float4* kp = reinterpret_cast<const float4*>(&sK[m * KPAD]);
            float s = 0.f;
#pragma unroll
            for (int j = 0; j < 8; j++) {
                float4 kk = kp[j];
                s += qr[j*4+0]*kk.x + qr[j*4+1]*kk.y + qr[j*4+2]*kk.z + qr[j*4+3]*kk.w;
            }
            if (s > mx) {
                float c = __expf(mx - s);
                sum *= c;
#pragma unroll
                for (int d = 0; d < DH; d++) o[d] *= c;
                mx = s;
            }
            float e = __expf(s - mx);
            sum += e;
            const float4* vp = reinterpret_cast<const float4*>(&sV[m * KPAD]);
#pragma unroll
            for (int j = 0; j < 8; j++) {
                float4 vv = vp[j];
                o[j*4+0] += e * vv.x; o[j*4+1] += e * vv.y;
                o[j*4+2] += e * vv.z; o[j*4+3] += e * vv.w;
            }
        }
    }

    float inv = 1.f / sum;
    float* ob = out + ((size_t)b * CH + h * DH) * HW;
#pragma unroll
    for (int d = 0; d < DH; d++) ob[d * HW + r] = o[d] * inv;
}

// ---------------------------------------------------------------------------
// Host launcher
// ---------------------------------------------------------------------------
extern "C" void kernel_launch(void* const* d_in, const int* in_sizes, int n_in,
                              void* d_out, int out_size)
{
    const float* x      = (const float*)d_in[0];
    const float* wq     = (const float*)d_in[1];
    const float* bq     = (const float*)d_in[2];
    const float* wk     = (const float*)d_in[3];
    const float* bk     = (const float*)d_in[4];
    const float* wv     = (const float*)d_in[5];
    const float* bv     = (const float*)d_in[6];
    const float* k_dw   = (const float*)d_in[7];
    const float* k_gn1s = (const float*)d_in[8];
    const float* k_gn1b = (const float*)d_in[9];
    const float* k_pw   = (const float*)d_in[10];
    const float* k_gn2s = (const float*)d_in[11];
    const float* k_gn2b = (const float*)d_in[12];
    const float* v_dw   = (const float*)d_in[13];
    const float* v_gn1s = (const float*)d_in[14];
    const float* v_gn1b = (const float*)d_in[15];
    const float* v_pw   = (const float*)d_in[16];
    const float* v_gn2s = (const float*)d_in[17];
    const float* v_gn2b = (const float*)d_in[18];
    float* out = (float*)d_out;

    float* base = nullptr;
    cudaGetSymbolAddress((void**)&base, g_scratch);
    float* q     = base + OFF_Q;
    float* kfull = base + OFF_KFULL;
    float* vfull = base + OFF_VFULL;
    float* kds   = base + OFF_KDS;
    float* vds   = base + OFF_VDS;
    float* kbr   = base + OFF_KBR;
    float* vbr   = base + OFF_VBR;

    // 1) q/k/v pointwise convs: (256x256) @ (256x1024) per batch
    {
        dim3 grid(HW / BN, CH / BM, BATCH);
        gemm_bias_kernel<<<grid, 256>>>(wq, x, bq, q,     CH, HW, CH);
        gemm_bias_kernel<<<grid, 256>>>(wk, x, bk, kfull, CH, HW, CH);
        gemm_bias_kernel<<<grid, 256>>>(wv, x, bv, vfull, CH, HW, CH);
    }

    // 2) depthwise downsample
    {
        int total = BATCH * CH * HWD;
        dwconv_s2_kernel<<<(total + 255) / 256, 256>>>(kfull, k_dw, kds);
        dwconv_s2_kernel<<<(total + 255) / 256, 256>>>(vfull, v_dw, vds);
    }

    // 3) GN1 + SiLU (in-place)
    {
        dim3 grid(GROUPS, BATCH);
        gn_silu_kernel<<<grid, HWD>>>(kds, k_gn1s, k_gn1b);
        gn_silu_kernel<<<grid, HWD>>>(vds, v_gn1s, v_gn1b);
    }

    // 4) pointwise conv (no bias): (256x256) @ (256x256) per batch
    {
        dim3 grid(HWD / BN, CH / BM, BATCH);
        gemm_bias_kernel<<<grid, 256>>>(k_pw, kds, nullptr, kbr, CH, HWD, CH);
        gemm_bias_kernel<<<grid, 256>>>(v_pw, vds, nullptr, vbr, CH, HWD, CH);
    }

    // 5) GN2 + SiLU (in-place)
    {
        dim3 grid(GROUPS, BATCH);
        gn_silu_kernel<<<grid, HWD>>>(kbr, k_gn2s, k_gn2b);
        gn_silu_kernel<<<grid, HWD>>>(vbr, v_gn2s, v_gn2b);
    }

    // 6) attention -> output (B,C,H,W)
    {
        dim3 grid(HW / QT, NH, BATCH);
        attn_kernel<<<grid, QT>>>(q, kbr, vbr, out);
    }
}

// round 6
// speedup vs baseline: 1.7837x; 1.7837x over previous
#include <cuda_runtime.h>
#include <cstdint>

// ---------------------------------------------------------------------------
// MobileMQA: q/k/v conv1x1 (tf32 MMA) -> (k,v) downsample branch (dw3x3 s2,
// GN+SiLU, pw1x1 tf32 MMA, GN+SiLU) -> MHA (N=1024 queries vs M=256 kv).
// B=32, C=256, H=W=32, heads=8, Dh=32, groups=32 (8 ch/group).
// ---------------------------------------------------------------------------

#define BATCH 32
#define CH 256
#define HW 1024          // 32*32
#define HWD 256          // 16*16
#define NH 8
#define DH 32
#define GROUPS 32
#define CPG 8            // channels per group
#define EPS 1e-5f

__device__ float g_scratch[33554432];

#define OFF_Q     0
#define OFF_KFULL 8388608
#define OFF_VFULL 16777216
#define OFF_KDS   25165824
#define OFF_VDS   27262976
#define OFF_KBR   29360128
#define OFF_VBR   31457280

// ---------------------------------------------------------------------------
// tf32 tensor-core GEMM: Y[b] = W (256x256) * X[b] (256xN) + bias.
// Block tile 128x64, BK=32, 256 threads (8 warps, 4x2), warp tile 32x32.
// mma.sync.aligned.m16n8k8.row.col.f32.tf32.tf32.f32
// sA stride 36 / sB stride 72 -> conflict-free fragment loads.
// ---------------------------------------------------------------------------
#define GK 256           // inner dim (fixed)
#define SASTRIDE 36
#define SBSTRIDE 72

__device__ __forceinline__ uint32_t f2tf32(float x) {
    float y;
    asm("cvt.rna.tf32.f32 %0, %1;" : "=f"(y) : "f"(x));
    return __float_as_uint(y);
}

__global__ void __launch_bounds__(256, 2)
gemm_tf32_kernel(const float* __restrict__ W,
                 const float* __restrict__ X,
                 const float* __restrict__ bias,
                 float* __restrict__ Y,
                 int N)
{
    const int b = blockIdx.z;
    const float* Xb = X + (size_t)b * GK * N;
    float* Yb = Y + (size_t)b * 256 * N;

    const int m0 = blockIdx.y * 128;
    const int n0 = blockIdx.x * 64;

    __shared__ float sA[128 * SASTRIDE];   // [m][k], 18.4 KB
    __shared__ float sB[32 * SBSTRIDE];    // [k][n],  9.2 KB

    const int t    = threadIdx.x;
    const int wid  = t >> 5;
    const int lane = t & 31;
    const int wm   = wid & 3;      // warp_m: 0..3  (rows 32 each)
    const int wn   = wid >> 2;     // warp_n: 0..1  (cols 32 each)
    const int g    = lane >> 2;    // group id 0..7
    const int tig  = lane & 3;     // thread-in-group 0..3

    float acc[2][4][4];
#pragma unroll
    for (int mt = 0; mt < 2; mt++)
#pragma unroll
        for (int nt = 0; nt < 4; nt++)
#pragma unroll
            for (int i = 0; i < 4; i++) acc[mt][nt][i] = 0.f;

    for (int k0 = 0; k0 < GK; k0 += 32) {
        // ---- fill sA: 128x32 = 1024 float4, 4 per thread ----
#pragma unroll
        for (int j = 0; j < 4; j++) {
            int i = t + j * 256;
            int m = i >> 3;            // 0..127
            int kq = i & 7;            // float4 index within row
            const float4 v = *reinterpret_cast<const float4*>(
                &W[(size_t)(m0 + m) * GK + k0 + kq * 4]);
            float4 o;
            o.x = __uint_as_float(f2tf32(v.x));
            o.y = __uint_as_float(f2tf32(v.y));
            o.z = __uint_as_float(f2tf32(v.z));
            o.w = __uint_as_float(f2tf32(v.w));
            *reinterpret_cast<float4*>(&sA[m * SASTRIDE + kq * 4]) = o;
        }
        // ---- fill sB: 32x64 = 512 float4, 2 per thread ----
#pragma unroll
        for (int j = 0; j < 2; j++) {
            int i = t + j * 256;
            int k = i >> 4;            // 0..31
            int nq = i & 15;           // float4 index within row
            const float4 v = *reinterpret_cast<const float4*>(
                &Xb[(size_t)(k0 + k) * N + n0 + nq * 4]);
            float4 o;
            o.x = __uint_as_float(f2tf32(v.x));
            o.y = __uint_as_float(f2tf32(v.y));
            o.z = __uint_as_float(f2tf32(v.z));
            o.w = __uint_as_float(f2tf32(v.w));
            *reinterpret_cast<float4*>(&sB[k * SBSTRIDE + nq * 4]) = o;
        }
        __syncthreads();

#pragma unroll
        for (int ks = 0; ks < 4; ks++) {
            const int kk = ks * 8;
            uint32_t af[2][4];
#pragma unroll
            for (int mt = 0; mt < 2; mt++) {
                int r = wm * 32 + mt * 16 + g;
                int c = kk + tig;
                af[mt][0] = __float_as_uint(sA[r * SASTRIDE + c]);
                af[mt][1] = __float_as_uint(sA[(r + 8) * SASTRIDE + c]);
                af[mt][2] = __float_as_uint(sA[r * SASTRIDE + c + 4]);
                af[mt][3] = __float_as_uint(sA[(r + 8) * SASTRIDE + c + 4]);
            }
            uint32_t bf[4][2];
#pragma unroll
            for (int nt = 0; nt < 4; nt++) {
                int cc = wn * 32 + nt * 8 + g;
                bf[nt][0] = __float_as_uint(sB[(kk + tig) * SBSTRIDE + cc]);
                bf[nt][1] = __float_as_uint(sB[(kk + tig + 4) * SBSTRIDE + cc]);
            }
#pragma unroll
            for (int mt = 0; mt < 2; mt++)
#pragma unroll
                for (int nt = 0; nt < 4; nt++) {
                    asm volatile(
                        "mma.sync.aligned.m16n8k8.row.col.f32.tf32.tf32.f32 "
                        "{%0,%1,%2,%3}, {%4,%5,%6,%7}, {%8,%9}, {%0,%1,%2,%3};"
                        : "+f"(acc[mt][nt][0]), "+f"(acc[mt][nt][1]),
                          "+f"(acc[mt][nt][2]), "+f"(acc[mt][nt][3])
                        : "r"(af[mt][0]), "r"(af[mt][1]),
                          "r"(af[mt][2]), "r"(af[mt][3]),
                          "r"(bf[nt][0]), "r"(bf[nt][1]));
                }
        }
        __syncthreads();
    }

    // epilogue: c0/c1 -> (row g, cols tig*2, tig*2+1); c2/c3 -> row g+8
#pragma unroll
    for (int mt = 0; mt < 2; mt++) {
        int r = m0 + wm * 32 + mt * 16 + g;
        float b0 = bias ? bias[r] : 0.f;
        float b1 = bias ? bias[r + 8] : 0.f;
#pragma unroll
        for (int nt = 0; nt < 4; nt++) {
            int c = n0 + wn * 32 + nt * 8 + tig * 2;
            float2 v0 = make_float2(acc[mt][nt][0] + b0, acc[mt][nt][1] + b0);
            float2 v1 = make_float2(acc[mt][nt][2] + b1, acc[mt][nt][3] + b1);
            *reinterpret_cast<float2*>(&Yb[(size_t)r * N + c]) = v0;
            *reinterpret_cast<float2*>(&Yb[(size_t)(r + 8) * N + c]) = v1;
        }
    }
}

// ---------------------------------------------------------------------------
// Depthwise 3x3 stride-2 pad-1: (B,C,32,32) -> (B,C,16,16)
// ---------------------------------------------------------------------------
__global__ void dwconv_s2_kernel(const float* __restrict__ in,
                                 const float* __restrict__ w,
                                 float* __restrict__ out)
{
    int idx = blockIdx.x * blockDim.x + threadIdx.x;
    if (idx >= BATCH * CH * HWD) return;
    int ox = idx & 15;
    int oy = (idx >> 4) & 15;
    int c  = (idx >> 8) & 255;
    int b  = idx >> 16;

    const float* ib = in + ((size_t)b * CH + c) * HW;
    const float* wc = w + c * 9;
    float acc = 0.f;
#pragma unroll
    for (int ky = 0; ky < 3; ky++) {
        int iy = 2 * oy - 1 + ky;
        if ((unsigned)iy >= 32u) continue;
#pragma unroll
        for (int kx = 0; kx < 3; kx++) {
            int ix = 2 * ox - 1 + kx;
            if ((unsigned)ix >= 32u) continue;
            acc += ib[iy * 32 + ix] * wc[ky * 3 + kx];
        }
    }
    out[idx] = acc;
}

// ---------------------------------------------------------------------------
// GroupNorm (32 groups of 8 ch over 16x16 spatial) + SiLU, in-place.
// ---------------------------------------------------------------------------
__global__ void gn_silu_kernel(float* __restrict__ x,
                               const float* __restrict__ scale,
                               const float* __restrict__ bias)
{
    const int g = blockIdx.x;
    const int b = blockIdx.y;
    float* base = x + ((size_t)b * CH + g * CPG) * HWD;
    const int p = threadIdx.x;

    float vals[CPG];
    float s = 0.f, s2 = 0.f;
#pragma unroll
    for (int c = 0; c < CPG; c++) {
        float v = base[c * HWD + p];
        vals[c] = v;
        s += v; s2 += v * v;
    }

#pragma unroll
    for (int o = 16; o > 0; o >>= 1) {
        s  += __shfl_down_sync(0xffffffffu, s,  o);
        s2 += __shfl_down_sync(0xffffffffu, s2, o);
    }
    __shared__ float rs[8], rs2[8];
    __shared__ float mu_s, rstd_s;
    int warp = p >> 5, lane = p & 31;
    if (lane == 0) { rs[warp] = s; rs2[warp] = s2; }
    __syncthreads();
    if (p == 0) {
        float S = 0.f, S2 = 0.f;
#pragma unroll
        for (int w = 0; w < 8; w++) { S += rs[w]; S2 += rs2[w]; }
        float mu  = S * (1.f / (CPG * HWD));
        float var = S2 * (1.f / (CPG * HWD)) - mu * mu;
        mu_s = mu;
        rstd_s = rsqrtf(var + EPS);
    }
    __syncthreads();
    float mu = mu_s, rstd = rstd_s;

#pragma unroll
    for (int c = 0; c < CPG; c++) {
        int ch = g * CPG + c;
        float y = (vals[c] - mu) * rstd * scale[ch] + bias[ch];
        y = y / (1.f + __expf(-y));
        base[c * HWD + p] = y;
    }
}

// ---------------------------------------------------------------------------
// Attention: per (b, head): q (1024 x 32), k/v (256 x 32). fp32 online softmax.
// ---------------------------------------------------------------------------
#define QT 128
#define MT 128
#define KPAD 36

__global__ void attn_kernel(const float* __restrict__ q,
                            const float* __restrict__ k,
                            const float* __restrict__ v,
                            float* __restrict__ out)
{
    __shared__ float sK[MT * KPAD];
    __shared__ float sV[MT * KPAD];

    const int b = blockIdx.z;
    const int h = blockIdx.y;
    const int r = blockIdx.x * QT + threadIdx.x;

    const float* qb = q + ((size_t)b * CH + h * DH) * HW;
    const float* kb = k + ((size_t)b * CH + h * DH) * HWD;
    const float* vb = v + ((size_t)b * CH + h * DH) * HWD;

    const float scale = 0.17677669529663687f;  // 1/sqrt(32)
    float qr[DH];
#pragma unroll
    for (int d = 0; d < DH; d++) qr[d] = qb[d * HW + r] * scale;

    float mx = -1e30f, sum = 0.f;
    float o[DH];
#pragma unroll
    for (int d = 0; d < DH; d++) o[d] = 0.f;

    for (int m0 = 0; m0 < HWD; m0 += MT) {
        __syncthreads();
        for (int i = threadIdx.x; i < MT * DH; i += QT) {
            int d = i >> 7;
            int m = i & (MT - 1);
            sK[m * KPAD + d] = kb[d * HWD + m0 + m];
            sV[m * KPAD + d] = vb[d * HWD + m0 + m];
        }
        __syncthreads();

        for (int m = 0; m < MT; m++) {
            const float4* kp = reinterpret_cast<const float4*>(&sK[m * KPAD]);
            float s = 0.f;
#pragma unroll
            for (int j = 0; j < 8; j++) {
                float4 kk = kp[j];
                s += qr[j*4+0]*kk.x + qr[j*4+1]*kk.y + qr[j*4+2]*kk.z + qr[j*4+3]*kk.w;
            }
            if (s > mx) {
                float c = __expf(mx - s);
                sum *= c;
#pragma unroll
                for (int d = 0; d < DH; d++) o[d] *= c;
                mx = s;
            }
            float e = __expf(s - mx);
            sum += e;
            const float4* vp = reinterpret_cast<const float4*>(&sV[m * KPAD]);
#pragma unroll
            for (int j = 0; j < 8; j++) {
                float4 vv = vp[j];
                o[j*4+0] += e * vv.x; o[j*4+1] += e * vv.y;
                o[j*4+2] += e * vv.z; o[j*4+3] += e * vv.w;
            }
        }
    }

    float inv = 1.f / sum;
    float* ob = out + ((size_t)b * CH + h * DH) * HW;
#pragma unroll
    for (int d = 0; d < DH; d++) ob[d * HW + r] = o[d] * inv;
}

// ---------------------------------------------------------------------------
// Host launcher
// ---------------------------------------------------------------------------
extern "C" void kernel_launch(void* const* d_in, const int* in_sizes, int n_in,
                              void* d_out, int out_size)
{
    const float* x      = (const float*)d_in[0];
    const float* wq     = (const float*)d_in[1];
    const float* bq     = (const float*)d_in[2];
    const float* wk     = (const float*)d_in[3];
    const float* bk     = (const float*)d_in[4];
    const float* wv     = (const float*)d_in[5];
    const float* bv     = (const float*)d_in[6];
    const float* k_dw   = (const float*)d_in[7];
    const float* k_gn1s = (const float*)d_in[8];
    const float* k_gn1b = (const float*)d_in[9];
    const float* k_pw   = (const float*)d_in[10];
    const float* k_gn2s = (const float*)d_in[11];
    const float* k_gn2b = (const float*)d_in[12];
    const float* v_dw   = (const float*)d_in[13];
    const float* v_gn1s = (const float*)d_in[14];
    const float* v_gn1b = (const float*)d_in[15];
    const float* v_pw   = (const float*)d_in[16];
    const float* v_gn2s = (const float*)d_in[17];
    const float* v_gn2b = (const float*)d_in[18];
    float* out = (float*)d_out;

    float* base = nullptr;
    cudaGetSymbolAddress((void**)&base, g_scratch);
    float* q     = base + OFF_Q;
    float* kfull = base + OFF_KFULL;
    float* vfull = base + OFF_VFULL;
    float* kds   = base + OFF_KDS;
    float* vds   = base + OFF_VDS;
    float* kbr   = base + OFF_KBR;
    float* vbr   = base + OFF_VBR;

    // 1) q/k/v pointwise convs: (256x256) @ (256x1024) per batch, tf32 MMA
    {
        dim3 grid(HW / 64, 2, BATCH);
        gemm_tf32_kernel<<<grid, 256>>>(wq, x, bq, q,     HW);
        gemm_tf32_kernel<<<grid, 256>>>(wk, x, bk, kfull, HW);
        gemm_tf32_kernel<<<grid, 256>>>(wv, x, bv, vfull, HW);
    }

    // 2) depthwise downsample
    {
        int total = BATCH * CH * HWD;
        dwconv_s2_kernel<<<(total + 255) / 256, 256>>>(kfull, k_dw, kds);
        dwconv_s2_kernel<<<(total + 255) / 256, 256>>>(vfull, v_dw, vds);
    }

    // 3) GN1 + SiLU (in-place)
    {
        dim3 grid(GROUPS, BATCH);
        gn_silu_kernel<<<grid, HWD>>>(kds, k_gn1s, k_gn1b);
        gn_silu_kernel<<<grid, HWD>>>(vds, v_gn1s, v_gn1b);
    }

    // 4) pointwise conv (no bias): (256x256) @ (256x256) per batch, tf32 MMA
    {
        dim3 grid(HWD / 64, 2, BATCH);
        gemm_tf32_kernel<<<grid, 256>>>(k_pw, kds, nullptr, kbr, HWD);
        gemm_tf32_kernel<<<grid, 256>>>(v_pw, vds, nullptr, vbr, HWD);
    }

    // 5) GN2 + SiLU (in-place)
    {
        dim3 grid(GROUPS, BATCH);
        gn_silu_kernel<<<grid, HWD>>>(kbr, k_gn2s, k_gn2b);
        gn_silu_kernel<<<grid, HWD>>>(vbr, v_gn2s, v_gn2b);
    }

    // 6) attention -> output (B,C,H,W)
    {
        dim3 grid(HW / QT, NH, BATCH);
        attn_kernel<<<grid, QT>>>(q, kbr, vbr, out);
    }
}

// round 7
// speedup vs baseline: 2.2072x; 1.2374x over previous
#include <cuda_runtime.h>
#include <cstdint>

// ---------------------------------------------------------------------------
// MobileMQA: q/k/v conv1x1 (tf32 MMA) -> (k,v) downsample branch (dw3x3 s2,
// GN+SiLU, pw1x1 tf32 MMA, GN+SiLU) -> MHA (tf32 MMA flash attention).
// B=32, C=256, H=W=32, heads=8, Dh=32, groups=32 (8 ch/group).
// ---------------------------------------------------------------------------

#define BATCH 32
#define CH 256
#define HW 1024          // 32*32
#define HWD 256          // 16*16
#define NH 8
#define DH 32
#define GROUPS 32
#define CPG 8            // channels per group
#define EPS 1e-5f

__device__ float g_scratch[33554432];

#define OFF_Q     0
#define OFF_KFULL 8388608
#define OFF_VFULL 16777216
#define OFF_KDS   25165824
#define OFF_VDS   27262976
#define OFF_KBR   29360128
#define OFF_VBR   31457280

__device__ __forceinline__ uint32_t f2tf32(float x) {
    float y;
    asm("cvt.rna.tf32.f32 %0, %1;" : "=f"(y) : "f"(x));
    return __float_as_uint(y);
}

__device__ __forceinline__ float fast_exp2(float x) {
    float y;
    asm("ex2.approx.ftz.f32 %0, %1;" : "=f"(y) : "f"(x));
    return y;
}

#define MMA_TF32(acc, a0,a1,a2,a3, b0,b1)                                   \
    asm volatile(                                                           \
        "mma.sync.aligned.m16n8k8.row.col.f32.tf32.tf32.f32 "               \
        "{%0,%1,%2,%3}, {%4,%5,%6,%7}, {%8,%9}, {%0,%1,%2,%3};"             \
        : "+f"((acc)[0]), "+f"((acc)[1]), "+f"((acc)[2]), "+f"((acc)[3])    \
        : "r"(a0), "r"(a1), "r"(a2), "r"(a3), "r"(b0), "r"(b1))

// ---------------------------------------------------------------------------
// tf32 tensor-core GEMM: Y[b] = W (256x256) * X[b] (256xN) + bias.
// ---------------------------------------------------------------------------
#define GK 256
#define SASTRIDE 36
#define SBSTRIDE 72

__global__ void __launch_bounds__(256, 2)
gemm_tf32_kernel(const float* __restrict__ W,
                 const float* __restrict__ X,
                 const float* __restrict__ bias,
                 float* __restrict__ Y,
                 int N)
{
    const int b = blockIdx.z;
    const float* Xb = X + (size_t)b * GK * N;
    float* Yb = Y + (size_t)b * 256 * N;

    const int m0 = blockIdx.y * 128;
    const int n0 = blockIdx.x * 64;

    __shared__ float sA[128 * SASTRIDE];
    __shared__ float sB[32 * SBSTRIDE];

    const int t    = threadIdx.x;
    const int wid  = t >> 5;
    const int lane = t & 31;
    const int wm   = wid & 3;
    const int wn   = wid >> 2;
    const int g    = lane >> 2;
    const int tig  = lane & 3;

    float acc[2][4][4];
#pragma unroll
    for (int mt = 0; mt < 2; mt++)
#pragma unroll
        for (int nt = 0; nt < 4; nt++)
#pragma unroll
            for (int i = 0; i < 4; i++) acc[mt][nt][i] = 0.f;

    for (int k0 = 0; k0 < GK; k0 += 32) {
#pragma unroll
        for (int j = 0; j < 4; j++) {
            int i = t + j * 256;
            int m = i >> 3;
            int kq = i & 7;
            const float4 v = *reinterpret_cast<const float4*>(
                &W[(size_t)(m0 + m) * GK + k0 + kq * 4]);
            float4 o;
            o.x = __uint_as_float(f2tf32(v.x));
            o.y = __uint_as_float(f2tf32(v.y));
            o.z = __uint_as_float(f2tf32(v.z));
            o.w = __uint_as_float(f2tf32(v.w));
            *reinterpret_cast<float4*>(&sA[m * SASTRIDE + kq * 4]) = o;
        }
#pragma unroll
        for (int j = 0; j < 2; j++) {
            int i = t + j * 256;
            int k = i >> 4;
            int nq = i & 15;
            const float4 v = *reinterpret_cast<const float4*>(
                &Xb[(size_t)(k0 + k) * N + n0 + nq * 4]);
            float4 o;
            o.x = __uint_as_float(f2tf32(v.x));
            o.y = __uint_as_float(f2tf32(v.y));
            o.z = __uint_as_float(f2tf32(v.z));
            o.w = __uint_as_float(f2tf32(v.w));
            *reinterpret_cast<float4*>(&sB[k * SBSTRIDE + nq * 4]) = o;
        }
        __syncthreads();

#pragma unroll
        for (int ks = 0; ks < 4; ks++) {
            const int kk = ks * 8;
            uint32_t af[2][4];
#pragma unroll
            for (int mt = 0; mt < 2; mt++) {
                int r = wm * 32 + mt * 16 + g;
                int c = kk + tig;
                af[mt][0] = __float_as_uint(sA[r * SASTRIDE + c]);
                af[mt][1] = __float_as_uint(sA[(r + 8) * SASTRIDE + c]);
                af[mt][2] = __float_as_uint(sA[r * SASTRIDE + c + 4]);
                af[mt][3] = __float_as_uint(sA[(r + 8) * SASTRIDE + c + 4]);
            }
            uint32_t bf[4][2];
#pragma unroll
            for (int nt = 0; nt < 4; nt++) {
                int cc = wn * 32 + nt * 8 + g;
                bf[nt][0] = __float_as_uint(sB[(kk + tig) * SBSTRIDE + cc]);
                bf[nt][1] = __float_as_uint(sB[(kk + tig + 4) * SBSTRIDE + cc]);
            }
#pragma unroll
            for (int mt = 0; mt < 2; mt++)
#pragma unroll
                for (int nt = 0; nt < 4; nt++)
                    MMA_TF32(acc[mt][nt], af[mt][0], af[mt][1], af[mt][2], af[mt][3],
                             bf[nt][0], bf[nt][1]);
        }
        __syncthreads();
    }

#pragma unroll
    for (int mt = 0; mt < 2; mt++) {
        int r = m0 + wm * 32 + mt * 16 + g;
        float b0 = bias ? bias[r] : 0.f;
        float b1 = bias ? bias[r + 8] : 0.f;
#pragma unroll
        for (int nt = 0; nt < 4; nt++) {
            int c = n0 + wn * 32 + nt * 8 + tig * 2;
            float2 v0 = make_float2(acc[mt][nt][0] + b0, acc[mt][nt][1] + b0);
            float2 v1 = make_float2(acc[mt][nt][2] + b1, acc[mt][nt][3] + b1);
            *reinterpret_cast<float2*>(&Yb[(size_t)r * N + c]) = v0;
            *reinterpret_cast<float2*>(&Yb[(size_t)(r + 8) * N + c]) = v1;
        }
    }
}

// ---------------------------------------------------------------------------
// Depthwise 3x3 stride-2 pad-1: (B,C,32,32) -> (B,C,16,16)
// ---------------------------------------------------------------------------
__global__ void dwconv_s2_kernel(const float* __restrict__ in,
                                 const float* __restrict__ w,
                                 float* __restrict__ out)
{
    int idx = blockIdx.x * blockDim.x + threadIdx.x;
    if (idx >= BATCH * CH * HWD) return;
    int ox = idx & 15;
    int oy = (idx >> 4) & 15;
    int c  = (idx >> 8) & 255;
    int b  = idx >> 16;

    const float* ib = in + ((size_t)b * CH + c) * HW;
    const float* wc = w + c * 9;
    float acc = 0.f;
#pragma unroll
    for (int ky = 0; ky < 3; ky++) {
        int iy = 2 * oy - 1 + ky;
        if ((unsigned)iy >= 32u) continue;
#pragma unroll
        for (int kx = 0; kx < 3; kx++) {
            int ix = 2 * ox - 1 + kx;
            if ((unsigned)ix >= 32u) continue;
            acc += ib[iy * 32 + ix] * wc[ky * 3 + kx];
        }
    }
    out[idx] = acc;
}

// ---------------------------------------------------------------------------
// GroupNorm (32 groups of 8 ch over 16x16 spatial) + SiLU, in-place.
// ---------------------------------------------------------------------------
__global__ void gn_silu_kernel(float* __restrict__ x,
                               const float* __restrict__ scale,
                               const float* __restrict__ bias)
{
    const int g = blockIdx.x;
    const int b = blockIdx.y;
    float* base = x + ((size_t)b * CH + g * CPG) * HWD;
    const int p = threadIdx.x;

    float vals[CPG];
    float s = 0.f, s2 = 0.f;
#pragma unroll
    for (int c = 0; c < CPG; c++) {
        float v = base[c * HWD + p];
        vals[c] = v;
        s += v; s2 += v * v;
    }

#pragma unroll
    for (int o = 16; o > 0; o >>= 1) {
        s  += __shfl_down_sync(0xffffffffu, s,  o);
        s2 += __shfl_down_sync(0xffffffffu, s2, o);
    }
    __shared__ float rs[8], rs2[8];
    __shared__ float mu_s, rstd_s;
    int warp = p >> 5, lane = p & 31;
    if (lane == 0) { rs[warp] = s; rs2[warp] = s2; }
    __syncthreads();
    if (p == 0) {
        float S = 0.f, S2 = 0.f;
#pragma unroll
        for (int w = 0; w < 8; w++) { S += rs[w]; S2 += rs2[w]; }
        float mu  = S * (1.f / (CPG * HWD));
        float var = S2 * (1.f / (CPG * HWD)) - mu * mu;
        mu_s = mu;
        rstd_s = rsqrtf(var + EPS);
    }
    __syncthreads();
    float mu = mu_s, rstd = rstd_s;

#pragma unroll
    for (int c = 0; c < CPG; c++) {
        int ch = g * CPG + c;
        float y = (vals[c] - mu) * rstd * scale[ch] + bias[ch];
        y = y / (1.f + __expf(-y));
        base[c * HWD + p] = y;
    }
}

// ---------------------------------------------------------------------------
// Tensor-core attention: block = one (b,h) x 128 queries, full M=256 KV.
// 8 warps; warp w owns query rows w*16..w*16+15 and all 256 kv columns.
// Scores in register C-fragments; single-pass softmax (max/sum via quad
// shuffles); P->A-fragment transpose via intra-quad shuffles; AV tf32 MMA.
// Dynamic smem: sQ[128x36] | sK[256x36] ([m][d]) | sV[32x260] ([d][m]).
// ---------------------------------------------------------------------------
#define AQ 128
#define AM 256
#define APAD 36
#define VSTRIDE 260
#define SMQ (AQ * APAD)                    // 4608 floats
#define SMK (AM * APAD)                    // 9216 floats
#define SMV (DH * VSTRIDE)                 // 8320 floats
#define ATTN_SMEM_BYTES ((SMQ + SMK + SMV) * 4)   // 88576 B

__global__ void __launch_bounds__(256, 1)
attn_mma_kernel(const float* __restrict__ q,
                const float* __restrict__ k,
                const float* __restrict__ v,
                float* __restrict__ out)
{
    extern __shared__ float sm[];
    float* sQ = sm;
    float* sK = sm + SMQ;
    float* sV = sm + SMQ + SMK;

    const int b  = blockIdx.z;
    const int h  = blockIdx.y;
    const int n0 = blockIdx.x * AQ;

    const float* qb = q + ((size_t)b * CH + h * DH) * HW;
    const float* kb = k + ((size_t)b * CH + h * DH) * HWD;
    const float* vb = v + ((size_t)b * CH + h * DH) * HWD;
    float* ob = out + ((size_t)b * CH + h * DH) * HW;

    const int t    = threadIdx.x;
    const int w    = t >> 5;
    const int lane = t & 31;
    const int g    = lane >> 2;
    const int tig  = lane & 3;
    const int r0   = w * 16;

    // scale * log2(e) folded into Q so ex2 suffices
    const float qscale = 0.17677669529663687f * 1.4426950408889634f;

    // ---- stage Q (transposed to [n][d]) ----
    for (int i = t; i < AQ * DH; i += 256) {
        int d = i >> 7;
        int n = i & 127;
        sQ[n * APAD + d] = __uint_as_float(f2tf32(qb[d * HW + n0 + n] * qscale));
    }
    // ---- stage K ([m][d]) and V ([d][m]) ----
    for (int i = t; i < AM * DH; i += 256) {
        int d = i >> 8;
        int m = i & 255;
        sK[m * APAD + d] = __uint_as_float(f2tf32(kb[d * HWD + m]));
        sV[d * VSTRIDE + m] = __uint_as_float(f2tf32(vb[d * HWD + m]));
    }
    __syncthreads();

    // ---- S = Q K^T (rows r0..r0+15, cols 0..255) ----
    float s[32][4];
#pragma unroll
    for (int nt = 0; nt < 32; nt++)
#pragma unroll
        for (int i = 0; i < 4; i++) s[nt][i] = 0.f;

#pragma unroll
    for (int ks = 0; ks < 4; ks++) {
        const int kk = ks * 8;
        uint32_t a0 = __float_as_uint(sQ[(r0 + g) * APAD + kk + tig]);
        uint32_t a1 = __float_as_uint(sQ[(r0 + g + 8) * APAD + kk + tig]);
        uint32_t a2 = __float_as_uint(sQ[(r0 + g) * APAD + kk + tig + 4]);
        uint32_t a3 = __float_as_uint(sQ[(r0 + g + 8) * APAD + kk + tig + 4]);
#pragma unroll
        for (int nt = 0; nt < 32; nt++) {
            uint32_t b0 = __float_as_uint(sK[(nt * 8 + g) * APAD + kk + tig]);
            uint32_t b1 = __float_as_uint(sK[(nt * 8 + g) * APAD + kk + tig + 4]);
            MMA_TF32(s[nt], a0, a1, a2, a3, b0, b1);
        }
    }
    __syncthreads();   // sQ free from here (reused for output staging)

    // ---- softmax over 256 cols; row g (c0,c1) and row g+8 (c2,c3) ----
    float mx0 = -1e30f, mx1 = -1e30f;
#pragma unroll
    for (int nt = 0; nt < 32; nt++) {
        mx0 = fmaxf(mx0, fmaxf(s[nt][0], s[nt][1]));
        mx1 = fmaxf(mx1, fmaxf(s[nt][2], s[nt][3]));
    }
    mx0 = fmaxf(mx0, __shfl_xor_sync(0xffffffffu, mx0, 1));
    mx0 = fmaxf(mx0, __shfl_xor_sync(0xffffffffu, mx0, 2));
    mx1 = fmaxf(mx1, __shfl_xor_sync(0xffffffffu, mx1, 1));
    mx1 = fmaxf(mx1, __shfl_xor_sync(0xffffffffu, mx1, 2));

    float sum0 = 0.f, sum1 = 0.f;
#pragma unroll
    for (int nt = 0; nt < 32; nt++) {
        s[nt][0] = fast_exp2(s[nt][0] - mx0);
        s[nt][1] = fast_exp2(s[nt][1] - mx0);
        s[nt][2] = fast_exp2(s[nt][2] - mx1);
        s[nt][3] = fast_exp2(s[nt][3] - mx1);
        sum0 += s[nt][0] + s[nt][1];
        sum1 += s[nt][2] + s[nt][3];
    }
    sum0 += __shfl_xor_sync(0xffffffffu, sum0, 1);
    sum0 += __shfl_xor_sync(0xffffffffu, sum0, 2);
    sum1 += __shfl_xor_sync(0xffffffffu, sum1, 1);
    sum1 += __shfl_xor_sync(0xffffffffu, sum1, 2);

    // ---- O = P V ----
    float o[4][4];
#pragma unroll
    for (int dt = 0; dt < 4; dt++)
#pragma unroll
        for (int i = 0; i < 4; i++) o[dt][i] = 0.f;

    const int src0 = (g << 2) + (tig >> 1);   // holder of col tig
    const int src1 = src0 + 2;                // holder of col tig+4
    const bool odd = (tig & 1);

#pragma unroll
    for (int mc = 0; mc < 32; mc++) {
        // A-fragment of P for kv chunk mc*8..mc*8+7 via in-quad shuffles
        float p00 = __shfl_sync(0xffffffffu, s[mc][0], src0);
        float p01 = __shfl_sync(0xffffffffu, s[mc][1], src0);
        float p20 = __shfl_sync(0xffffffffu, s[mc][0], src1);
        float p21 = __shfl_sync(0xffffffffu, s[mc][1], src1);
        float p10 = __shfl_sync(0xffffffffu, s[mc][2], src0);
        float p11 = __shfl_sync(0xffffffffu, s[mc][3], src0);
        float p30 = __shfl_sync(0xffffffffu, s[mc][2], src1);
        float p31 = __shfl_sync(0xffffffffu, s[mc][3], src1);
        uint32_t a0 = f2tf32(odd ? p01 : p00);
        uint32_t a1 = f2tf32(odd ? p11 : p10);
        uint32_t a2 = f2tf32(odd ? p21 : p20);
        uint32_t a3 = f2tf32(odd ? p31 : p30);
#pragma unroll
        for (int dt = 0; dt < 4; dt++) {
            uint32_t b0 = __float_as_uint(sV[(dt * 8 + g) * VSTRIDE + mc * 8 + tig]);
            uint32_t b1 = __float_as_uint(sV[(dt * 8 + g) * VSTRIDE + mc * 8 + tig + 4]);
            MMA_TF32(o[dt], a0, a1, a2, a3, b0, b1);
        }
    }

    // ---- normalize and stage into sQ[n][d] for coalesced output ----
    float inv0 = 1.f / sum0;
    float inv1 = 1.f / sum1;
#pragma unroll
    for (int dt = 0; dt < 4; dt++) {
        int c = dt * 8 + tig * 2;
        sQ[(r0 + g) * APAD + c]     = o[dt][0] * inv0;
        sQ[(r0 + g) * APAD + c + 1] = o[dt][1] * inv0;
        sQ[(r0 + g + 8) * APAD + c]     = o[dt][2] * inv1;
        sQ[(r0 + g + 8) * APAD + c + 1] = o[dt][3] * inv1;
    }
    __syncthreads();

    for (int i = t; i < AQ * DH; i += 256) {
        int d = i >> 7;
        int n = i & 127;
        ob[d * HW + n0 + n] = sQ[n * APAD + d];
    }
}

// ---------------------------------------------------------------------------
// Host launcher
// ---------------------------------------------------------------------------
extern "C" void kernel_launch(void* const* d_in, const int* in_sizes, int n_in,
                              void* d_out, int out_size)
{
    const float* x      = (const float*)d_in[0];
    const float* wq     = (const float*)d_in[1];
    const float* bq     = (const float*)d_in[2];
    const float* wk     = (const float*)d_in[3];
    const float* bk     = (const float*)d_in[4];
    const float* wv     = (const float*)d_in[5];
    const float* bv     = (const float*)d_in[6];
    const float* k_dw   = (const float*)d_in[7];
    const float* k_gn1s = (const float*)d_in[8];
    const float* k_gn1b = (const float*)d_in[9];
    const float* k_pw   = (const float*)d_in[10];
    const float* k_gn2s = (const float*)d_in[11];
    const float* k_gn2b = (const float*)d_in[12];
    const float* v_dw   = (const float*)d_in[13];
    const float* v_gn1s = (const float*)d_in[14];
    const float* v_gn1b = (const float*)d_in[15];
    const float* v_pw   = (const float*)d_in[16];
    const float* v_gn2s = (const float*)d_in[17];
    const float* v_gn2b = (const float*)d_in[18];
    float* out = (float*)d_out;

    float* base = nullptr;
    cudaGetSymbolAddress((void**)&base, g_scratch);
    float* q     = base + OFF_Q;
    float* kfull = base + OFF_KFULL;
    float* vfull = base + OFF_VFULL;
    float* kds   = base + OFF_KDS;
    float* vds   = base + OFF_VDS;
    float* kbr   = base + OFF_KBR;
    float* vbr   = base + OFF_VBR;

    // opt-in smem for attention (config call, not an allocation)
    cudaFuncSetAttribute(attn_mma_kernel,
                         cudaFuncAttributeMaxDynamicSharedMemorySize,
                         ATTN_SMEM_BYTES);

    // 1) q/k/v pointwise convs: (256x256) @ (256x1024) per batch, tf32 MMA
    {
        dim3 grid(HW / 64, 2, BATCH);
        gemm_tf32_kernel<<<grid, 256>>>(wq, x, bq, q,     HW);
        gemm_tf32_kernel<<<grid, 256>>>(wk, x, bk, kfull, HW);
        gemm_tf32_kernel<<<grid, 256>>>(wv, x, bv, vfull, HW);
    }

    // 2) depthwise downsample
    {
        int total = BATCH * CH * HWD;
        dwconv_s2_kernel<<<(total + 255) / 256, 256>>>(kfull, k_dw, kds);
        dwconv_s2_kernel<<<(total + 255) / 256, 256>>>(vfull, v_dw, vds);
    }

    // 3) GN1 + SiLU (in-place)
    {
        dim3 grid(GROUPS, BATCH);
        gn_silu_kernel<<<grid, HWD>>>(kds, k_gn1s, k_gn1b);
        gn_silu_kernel<<<grid, HWD>>>(vds, v_gn1s, v_gn1b);
    }

    // 4) pointwise conv (no bias): (256x256) @ (256x256) per batch, tf32 MMA
    {
        dim3 grid(HWD / 64, 2, BATCH);
        gemm_tf32_kernel<<<grid, 256>>>(k_pw, kds, nullptr, kbr, HWD);
        gemm_tf32_kernel<<<grid, 256>>>(v_pw, vds, nullptr, vbr, HWD);
    }

    // 5) GN2 + SiLU (in-place)
    {
        dim3 grid(GROUPS, BATCH);
        gn_silu_kernel<<<grid, HWD>>>(kbr, k_gn2s, k_gn2b);
        gn_silu_kernel<<<grid, HWD>>>(vbr, v_gn2s, v_gn2b);
    }

    // 6) attention -> output (B,C,H,W), tf32 MMA
    {
        dim3 grid(HW / AQ, NH, BATCH);
        attn_mma_kernel<<<grid, 256, ATTN_SMEM_BYTES>>>(q, kbr, vbr, out);
    }
}

// round 10
// speedup vs baseline: 2.9003x; 1.3140x over previous
#include <cuda_runtime.h>
#include <cuda_fp16.h>
#include <cstdint>

// ---------------------------------------------------------------------------
// MobileMQA: q/k/v conv1x1 (tf32 MMA) -> (k,v) downsample branch (fused
// dw3x3s2+GN+SiLU, pw1x1 tf32 MMA, GN+SiLU) -> MHA (fp16 MMA flash attn).
// B=32, C=256, H=W=32, heads=8, Dh=32, groups=32 (8 ch/group).
// ---------------------------------------------------------------------------

#define BATCH 32
#define CH 256
#define HW 1024          // 32*32
#define HWD 256          // 16*16
#define NH 8
#define DH 32
#define GROUPS 32
#define CPG 8            // channels per group
#define EPS 1e-5f

__device__ float g_scratch[33554432];

#define OFF_Q     0
#define OFF_KFULL 8388608
#define OFF_VFULL 16777216
#define OFF_KDS   25165824
#define OFF_VDS   27262976
#define OFF_KBR   29360128
#define OFF_VBR   31457280

__device__ __forceinline__ uint32_t f2tf32(float x) {
    float y;
    asm("cvt.rna.tf32.f32 %0, %1;" : "=f"(y) : "f"(x));
    return __float_as_uint(y);
}

__device__ __forceinline__ float fast_exp2(float x) {
    float y;
    asm("ex2.approx.ftz.f32 %0, %1;" : "=f"(y) : "f"(x));
    return y;
}

__device__ __forceinline__ uint32_t pack2h(float a, float b) {
    __half2 h = __floats2half2_rn(a, b);
    return *reinterpret_cast<uint32_t*>(&h);
}

#define MMA_TF32(acc, a0,a1,a2,a3, b0,b1)                                   \
    asm volatile(                                                           \
        "mma.sync.aligned.m16n8k8.row.col.f32.tf32.tf32.f32 "               \
        "{%0,%1,%2,%3}, {%4,%5,%6,%7}, {%8,%9}, {%0,%1,%2,%3};"             \
        : "+f"((acc)[0]), "+f"((acc)[1]), "+f"((acc)[2]), "+f"((acc)[3])    \
        : "r"(a0), "r"(a1), "r"(a2), "r"(a3), "r"(b0), "r"(b1))

#define MMA_F16(acc, a0,a1,a2,a3, b0,b1)                                    \
    asm volatile(                                                           \
        "mma.sync.aligned.m16n8k16.row.col.f32.f16.f16.f32 "                \
        "{%0,%1,%2,%3}, {%4,%5,%6,%7}, {%8,%9}, {%0,%1,%2,%3};"             \
        : "+f"((acc)[0]), "+f"((acc)[1]), "+f"((acc)[2]), "+f"((acc)[3])    \
        : "r"(a0), "r"(a1), "r"(a2), "r"(a3), "r"(b0), "r"(b1))

// ---------------------------------------------------------------------------
// tf32 tensor-core GEMM: Y[b] = W (256x256) * X[b] (256xN) + bias.
// ---------------------------------------------------------------------------
#define GK 256
#define SASTRIDE 36
#define SBSTRIDE 72

__global__ void __launch_bounds__(256, 2)
gemm_tf32_kernel(const float* __restrict__ W,
                 const float* __restrict__ X,
                 const float* __restrict__ bias,
                 float* __restrict__ Y,
                 int N)
{
    const int b = blockIdx.z;
    const float* Xb = X + (size_t)b * GK * N;
    float* Yb = Y + (size_t)b * 256 * N;

    const int m0 = blockIdx.y * 128;
    const int n0 = blockIdx.x * 64;

    __shared__ float sA[128 * SASTRIDE];
    __shared__ float sB[32 * SBSTRIDE];

    const int t    = threadIdx.x;
    const int wid  = t >> 5;
    const int lane = t & 31;
    const int wm   = wid & 3;
    const int wn   = wid >> 2;
    const int g    = lane >> 2;
    const int tig  = lane & 3;

    float acc[2][4][4];
#pragma unroll
    for (int mt = 0; mt < 2; mt++)
#pragma unroll
        for (int nt = 0; nt < 4; nt++)
#pragma unroll
            for (int i = 0; i < 4; i++) acc[mt][nt][i] = 0.f;

    for (int k0 = 0; k0 < GK; k0 += 32) {
#pragma unroll
        for (int j = 0; j < 4; j++) {
            int i = t + j * 256;
            int m = i >> 3;
            int kq = i & 7;
            const float4 v = *reinterpret_cast<const float4*>(
                &W[(size_t)(m0 + m) * GK + k0 + kq * 4]);
            float4 o;
            o.x = __uint_as_float(f2tf32(v.x));
            o.y = __uint_as_float(f2tf32(v.y));
            o.z = __uint_as_float(f2tf32(v.z));
            o.w = __uint_as_float(f2tf32(v.w));
            *reinterpret_cast<float4*>(&sA[m * SASTRIDE + kq * 4]) = o;
        }
#pragma unroll
        for (int j = 0; j < 2; j++) {
            int i = t + j * 256;
            int k = i >> 4;
            int nq = i & 15;
            const float4 v = *reinterpret_cast<const float4*>(
                &Xb[(size_t)(k0 + k) * N + n0 + nq * 4]);
            float4 o;
            o.x = __uint_as_float(f2tf32(v.x));
            o.y = __uint_as_float(f2tf32(v.y));
            o.z = __uint_as_float(f2tf32(v.z));
            o.w = __uint_as_float(f2tf32(v.w));
            *reinterpret_cast<float4*>(&sB[k * SBSTRIDE + nq * 4]) = o;
        }
        __syncthreads();

#pragma unroll
        for (int ks = 0; ks < 4; ks++) {
            const int kk = ks * 8;
            uint32_t af[2][4];
#pragma unroll
            for (int mt = 0; mt < 2; mt++) {
                int r = wm * 32 + mt * 16 + g;
                int c = kk + tig;
                af[mt][0] = __float_as_uint(sA[r * SASTRIDE + c]);
                af[mt][1] = __float_as_uint(sA[(r + 8) * SASTRIDE + c]);
                af[mt][2] = __float_as_uint(sA[r * SASTRIDE + c + 4]);
                af[mt][3] = __float_as_uint(sA[(r + 8) * SASTRIDE + c + 4]);
            }
            uint32_t bf[4][2];
#pragma unroll
            for (int nt = 0; nt < 4; nt++) {
                int cc = wn * 32 + nt * 8 + g;
                bf[nt][0] = __float_as_uint(sB[(kk + tig) * SBSTRIDE + cc]);
                bf[nt][1] = __float_as_uint(sB[(kk + tig + 4) * SBSTRIDE + cc]);
            }
#pragma unroll
            for (int mt = 0; mt < 2; mt++)
#pragma unroll
                for (int nt = 0; nt < 4; nt++)
                    MMA_TF32(acc[mt][nt], af[mt][0], af[mt][1], af[mt][2], af[mt][3],
                             bf[nt][0], bf[nt][1]);
        }
        __syncthreads();
    }

#pragma unroll
    for (int mt = 0; mt < 2; mt++) {
        int r = m0 + wm * 32 + mt * 16 + g;
        float b0 = bias ? bias[r] : 0.f;
        float b1 = bias ? bias[r + 8] : 0.f;
#pragma unroll
        for (int nt = 0; nt < 4; nt++) {
            int c = n0 + wn * 32 + nt * 8 + tig * 2;
            float2 v0 = make_float2(acc[mt][nt][0] + b0, acc[mt][nt][1] + b0);
            float2 v1 = make_float2(acc[mt][nt][2] + b1, acc[mt][nt][3] + b1);
            *reinterpret_cast<float2*>(&Yb[(size_t)r * N + c]) = v0;
            *reinterpret_cast<float2*>(&Yb[(size_t)(r + 8) * N + c]) = v1;
        }
    }
}

// ---------------------------------------------------------------------------
// Fused depthwise 3x3 s2 + GroupNorm + SiLU.
// grid (GROUPS, BATCH), 256 threads = one output pixel each, 8 channels/group.
// ---------------------------------------------------------------------------
__global__ void dwgn_silu_kernel(const float* __restrict__ in,
                                 const float* __restrict__ dw,
                                 const float* __restrict__ scale,
                                 const float* __restrict__ bias,
                                 float* __restrict__ out)
{
    const int gr = blockIdx.x;
    const int b  = blockIdx.y;
    const int p  = threadIdx.x;
    const int ox = p & 15;
    const int oy = p >> 4;

    float vals[CPG];
    float s = 0.f, s2 = 0.f;
#pragma unroll
    for (int c = 0; c < CPG; c++) {
        int ch = gr * CPG + c;
        const float* ib = in + ((size_t)b * CH + ch) * HW;
        const float* wc = dw + ch * 9;
        float acc = 0.f;
#pragma unroll
        for (int ky = 0; ky < 3; ky++) {
            int iy = 2 * oy - 1 + ky;
            if ((unsigned)iy >= 32u) continue;
#pragma unroll
            for (int kx = 0; kx < 3; kx++) {
                int ix = 2 * ox - 1 + kx;
                if ((unsigned)ix >= 32u) continue;
                acc += ib[iy * 32 + ix] * wc[ky * 3 + kx];
            }
        }
        vals[c] = acc;
        s += acc; s2 += acc * acc;
    }

#pragma unroll
    for (int o = 16; o > 0; o >>= 1) {
        s  += __shfl_down_sync(0xffffffffu, s,  o);
        s2 += __shfl_down_sync(0xffffffffu, s2, o);
    }
    __shared__ float rs[8], rs2[8];
    __shared__ float mu_s, rstd_s;
    int warp = p >> 5, lane = p & 31;
    if (lane == 0) { rs[warp] = s; rs2[warp] = s2; }
    __syncthreads();
    if (p == 0) {
        float S = 0.f, S2 = 0.f;
#pragma unroll
        for (int w = 0; w < 8; w++) { S += rs[w]; S2 += rs2[w]; }
        float mu  = S * (1.f / (CPG * HWD));
        float var = S2 * (1.f / (CPG * HWD)) - mu * mu;
        mu_s = mu;
        rstd_s = rsqrtf(var + EPS);
    }
    __syncthreads();
    float mu = mu_s, rstd = rstd_s;

#pragma unroll
    for (int c = 0; c < CPG; c++) {
        int ch = gr * CPG + c;
        float y = (vals[c] - mu) * rstd * scale[ch] + bias[ch];
        y = y / (1.f + __expf(-y));
        out[((size_t)b * CH + ch) * HWD + p] = y;
    }
}

// ---------------------------------------------------------------------------
// GroupNorm + SiLU, in-place (after pw conv).
// ---------------------------------------------------------------------------
__global__ void gn_silu_kernel(float* __restrict__ x,
                               const float* __restrict__ scale,
                               const float* __restrict__ bias)
{
    const int g = blockIdx.x;
    const int b = blockIdx.y;
    float* base = x + ((size_t)b * CH + g * CPG) * HWD;
    const int p = threadIdx.x;

    float vals[CPG];
    float s = 0.f, s2 = 0.f;
#pragma unroll
    for (int c = 0; c < CPG; c++) {
        float v = base[c * HWD + p];
        vals[c] = v;
        s += v; s2 += v * v;
    }

#pragma unroll
    for (int o = 16; o > 0; o >>= 1) {
        s  += __shfl_down_sync(0xffffffffu, s,  o);
        s2 += __shfl_down_sync(0xffffffffu, s2, o);
    }
    __shared__ float rs[8], rs2[8];
    __shared__ float mu_s, rstd_s;
    int warp = p >> 5, lane = p & 31;
    if (lane == 0) { rs[warp] = s; rs2[warp] = s2; }
    __syncthreads();
    if (p == 0) {
        float S = 0.f, S2 = 0.f;
#pragma unroll
        for (int w = 0; w < 8; w++) { S += rs[w]; S2 += rs2[w]; }
        float mu  = S * (1.f / (CPG * HWD));
        float var = S2 * (1.f / (CPG * HWD)) - mu * mu;
        mu_s = mu;
        rstd_s = rsqrtf(var + EPS);
    }
    __syncthreads();
    float mu = mu_s, rstd = rstd_s;

#pragma unroll
    for (int c = 0; c < CPG; c++) {
        int ch = g * CPG + c;
        float y = (vals[c] - mu) * rstd * scale[ch] + bias[ch];
        y = y / (1.f + __expf(-y));
        base[c * HWD + p] = y;
    }
}

// ---------------------------------------------------------------------------
// fp16 tensor-core flash attention. Block = (b,h) x 128 queries, M=256 KV.
// 8 warps x 16 query rows. m16n8k16; online softmax over 2 chunks of 128 KV
// (s[16][4] regs -> ~105 regs -> 2 blocks/SM). fp16 C-frag == A-frag layout
// so P feeds PV with zero shuffles. All fragment LDS conflict-free.
// smem: sQ half[128][40] | sK half[256][40] | sV half[32][264]  (46.5 KB)
// Output staged as float[128][33] overlaid on sQ/sK.
// ---------------------------------------------------------------------------
#define AQ 128
#define AM 256
#define QPAD 40      // halves per row (sQ, sK)
#define VPAD 264     // halves per row (sV)
#define SMEM_HALVES (AQ*QPAD + AM*QPAD + DH*VPAD)   // 23808 halves = 47616 B

__global__ void __launch_bounds__(256, 2)
attn_fp16_kernel(const float* __restrict__ q,
                 const float* __restrict__ k,
                 const float* __restrict__ v,
                 float* __restrict__ out)
{
    __shared__ __align__(16) __half smem[SMEM_HALVES];
    __half* sQ = smem;
    __half* sK = smem + AQ * QPAD;
    __half* sV = smem + AQ * QPAD + AM * QPAD;
    float* sO = reinterpret_cast<float*>(smem);   // overlay (post-compute)

    const int b  = blockIdx.z;
    const int h  = blockIdx.y;
    const int n0 = blockIdx.x * AQ;

    const float* qb = q + ((size_t)b * CH + h * DH) * HW;
    const float* kb = k + ((size_t)b * CH + h * DH) * HWD;
    const float* vb = v + ((size_t)b * CH + h * DH) * HWD;
    float* ob = out + ((size_t)b * CH + h * DH) * HW;

    const int t    = threadIdx.x;
    const int w    = t >> 5;
    const int lane = t & 31;
    const int g    = lane >> 2;
    const int tig  = lane & 3;
    const int r0   = w * 16;

    const float qscale = 0.17677669529663687f * 1.4426950408889634f; // /sqrt(32)*log2e

    // ---- stage Q [n][d], K [m][d], V [d][m] as fp16 ----
    for (int i = t; i < AQ * DH; i += 256) {
        int d = i >> 7, n = i & 127;
        sQ[n * QPAD + d] = __float2half(qb[d * HW + n0 + n] * qscale);
    }
    for (int i = t; i < AM * DH; i += 256) {
        int d = i >> 8, m = i & 255;
        sK[m * QPAD + d] = __float2half(kb[d * HWD + m]);
        sV[d * VPAD + m] = __float2half(vb[d * HWD + m]);
    }
    __syncthreads();

    float o[4][4];
#pragma unroll
    for (int dt = 0; dt < 4; dt++)
#pragma unroll
        for (int i = 0; i < 4; i++) o[dt][i] = 0.f;
    float mx0 = -1e30f, mx1 = -1e30f, sum0 = 0.f, sum1 = 0.f;

#pragma unroll
    for (int chunk = 0; chunk < 2; chunk++) {
        const int c0 = chunk * 128;

        // ---- S chunk = Q K^T : 16 col-tiles of 8 ----
        float s[16][4];
#pragma unroll
        for (int nt = 0; nt < 16; nt++)
#pragma unroll
            for (int i = 0; i < 4; i++) s[nt][i] = 0.f;

#pragma unroll
        for (int ks = 0; ks < 2; ks++) {
            const int kk = ks * 16;
            uint32_t a0 = *reinterpret_cast<const uint32_t*>(&sQ[(r0 + g) * QPAD + kk + 2 * tig]);
            uint32_t a1 = *reinterpret_cast<const uint32_t*>(&sQ[(r0 + g + 8) * QPAD + kk + 2 * tig]);
            uint32_t a2 = *reinterpret_cast<const uint32_t*>(&sQ[(r0 + g) * QPAD + kk + 2 * tig + 8]);
            uint32_t a3 = *reinterpret_cast<const uint32_t*>(&sQ[(r0 + g + 8) * QPAD + kk + 2 * tig + 8]);
#pragma unroll
            for (int nt = 0; nt < 16; nt++) {
                int m = c0 + nt * 8 + g;
                uint32_t b0 = *reinterpret_cast<const uint32_t*>(&sK[m * QPAD + kk + 2 * tig]);
                uint32_t b1 = *reinterpret_cast<const uint32_t*>(&sK[m * QPAD + kk + 2 * tig + 8]);
                MMA_F16(s[nt], a0, a1, a2, a3, b0, b1);
            }
        }

        // ---- online softmax update ----
        float cm0 = -1e30f, cm1 = -1e30f;
#pragma unroll
        for (int nt = 0; nt < 16; nt++) {
            cm0 = fmaxf(cm0, fmaxf(s[nt][0], s[nt][1]));
            cm1 = fmaxf(cm1, fmaxf(s[nt][2], s[nt][3]));
        }
        cm0 = fmaxf(cm0, __shfl_xor_sync(0xffffffffu, cm0, 1));
        cm0 = fmaxf(cm0, __shfl_xor_sync(0xffffffffu, cm0, 2));
        cm1 = fmaxf(cm1, __shfl_xor_sync(0xffffffffu, cm1, 1));
        cm1 = fmaxf(cm1, __shfl_xor_sync(0xffffffffu, cm1, 2));

        float nm0 = fmaxf(mx0, cm0);
        float nm1 = fmaxf(mx1, cm1);
        float f0 = fast_exp2(mx0 - nm0);
        float f1 = fast_exp2(mx1 - nm1);
        sum0 *= f0; sum1 *= f1;
#pragma unroll
        for (int dt = 0; dt < 4; dt++) {
            o[dt][0] *= f0; o[dt][1] *= f0;
            o[dt][2] *= f1; o[dt][3] *= f1;
        }
        mx0 = nm0; mx1 = nm1;

        // ---- P = exp2(S - m), packed to fp16 A-frags in place; O += P V ----
#pragma unroll
        for (int mc = 0; mc < 8; mc++) {
            float p00 = fast_exp2(s[2*mc][0] - mx0);
            float p01 = fast_exp2(s[2*mc][1] - mx0);
            float p02 = fast_exp2(s[2*mc][2] - mx1);
            float p03 = fast_exp2(s[2*mc][3] - mx1);
            float p10 = fast_exp2(s[2*mc+1][0] - mx0);
            float p11 = fast_exp2(s[2*mc+1][1] - mx0);
            float p12 = fast_exp2(s[2*mc+1][2] - mx1);
            float p13 = fast_exp2(s[2*mc+1][3] - mx1);
            sum0 += p00 + p01 + p10 + p11;
            sum1 += p02 + p03 + p12 + p13;
            uint32_t a0 = pack2h(p00, p01);
            uint32_t a1 = pack2h(p02, p03);
            uint32_t a2 = pack2h(p10, p11);
            uint32_t a3 = pack2h(p12, p13);
            const int mbase = c0 + mc * 16 + 2 * tig;
#pragma unroll
            for (int dt = 0; dt < 4; dt++) {
                int dd = dt * 8 + g;
                uint32_t b0 = *reinterpret_cast<const uint32_t*>(&sV[dd * VPAD + mbase]);
                uint32_t b1 = *reinterpret_cast<const uint32_t*>(&sV[dd * VPAD + mbase + 8]);
                MMA_F16(o[dt], a0, a1, a2, a3, b0, b1);
            }
        }
    }

    sum0 += __shfl_xor_sync(0xffffffffu, sum0, 1);
    sum0 += __shfl_xor_sync(0xffffffffu, sum0, 2);
    sum1 += __shfl_xor_sync(0xffffffffu, sum1, 1);
    sum1 += __shfl_xor_sync(0xffffffffu, sum1, 2);
    float inv0 = 1.f / sum0;
    float inv1 = 1.f / sum1;

    __syncthreads();   // all warps done reading sQ/sK before overlay write

    // ---- stage O[q][d] (pad 33) for coalesced store ----
#pragma unroll
    for (int dt = 0; dt < 4; dt++) {
        int c = dt * 8 + tig * 2;
        sO[(r0 + g) * 33 + c]     = o[dt][0] * inv0;
        sO[(r0 + g) * 33 + c + 1] = o[dt][1] * inv0;
        sO[(r0 + g + 8) * 33 + c]     = o[dt][2] * inv1;
        sO[(r0 + g + 8) * 33 + c + 1] = o[dt][3] * inv1;
    }
    __syncthreads();

    for (int i = t; i < AQ * DH; i += 256) {
        int d = i >> 7, n = i & 127;
        ob[d * HW + n0 + n] = sO[n * 33 + d];
    }
}

// ---------------------------------------------------------------------------
// Host launcher
// ---------------------------------------------------------------------------
extern "C" void kernel_launch(void* const* d_in, const int* in_sizes, int n_in,
                              void* d_out, int out_size)
{
    const float* x      = (const float*)d_in[0];
    const float* wq     = (const float*)d_in[1];
    const float* bq     = (const float*)d_in[2];
    const float* wk     = (const float*)d_in[3];
    const float* bk     = (const float*)d_in[4];
    const float* wv     = (const float*)d_in[5];
    const float* bv     = (const float*)d_in[6];
    const float* k_dw   = (const float*)d_in[7];
    const float* k_gn1s = (const float*)d_in[8];
    const float* k_gn1b = (const float*)d_in[9];
    const float* k_pw   = (const float*)d_in[10];
    const float* k_gn2s = (const float*)d_in[11];
    const float* k_gn2b = (const float*)d_in[12];
    const float* v_dw   = (const float*)d_in[13];
    const float* v_gn1s = (const float*)d_in[14];
    const float* v_gn1b = (const float*)d_in[15];
    const float* v_pw   = (const float*)d_in[16];
    const float* v_gn2s = (const float*)d_in[17];
    const float* v_gn2b = (const float*)d_in[18];
    float* out = (float*)d_out;

    float* base = nullptr;
    cudaGetSymbolAddress((void**)&base, g_scratch);
    float* q     = base + OFF_Q;
    float* kfull = base + OFF_KFULL;
    float* vfull = base + OFF_VFULL;
    float* kds   = base + OFF_KDS;
    float* vds   = base + OFF_VDS;
    float* kbr   = base + OFF_KBR;
    float* vbr   = base + OFF_VBR;

    // 1) q/k/v pointwise convs: (256x256) @ (256x1024) per batch, tf32 MMA
    {
        dim3 grid(HW / 64, 2, BATCH);
        gemm_tf32_kernel<<<grid, 256>>>(wq, x, bq, q,     HW);
        gemm_tf32_kernel<<<grid, 256>>>(wk, x, bk, kfull, HW);
        gemm_tf32_kernel<<<grid, 256>>>(wv, x, bv, vfull, HW);
    }

    // 2) fused depthwise s2 + GN1 + SiLU
    {
        dim3 grid(GROUPS, BATCH);
        dwgn_silu_kernel<<<grid, HWD>>>(kfull, k_dw, k_gn1s, k_gn1b, kds);
        dwgn_silu_kernel<<<grid, HWD>>>(vfull, v_dw, v_gn1s, v_gn1b, vds);
    }

    // 3) pointwise conv (no bias): (256x256) @ (256x256) per batch, tf32 MMA
    {
        dim3 grid(HWD / 64, 2, BATCH);
        gemm_tf32_kernel<<<grid, 256>>>(k_pw, kds, nullptr, kbr, HWD);
        gemm_tf32_kernel<<<grid, 256>>>(v_pw, vds, nullptr, vbr, HWD);
    }

    // 4) GN2 + SiLU (in-place)
    {
        dim3 grid(GROUPS, BATCH);
        gn_silu_kernel<<<grid, HWD>>>(kbr, k_gn2s, k_gn2b);
        gn_silu_kernel<<<grid, HWD>>>(vbr, v_gn2s, v_gn2b);
    }

    // 5) attention -> output (B,C,H,W), fp16 MMA
    {
        dim3 grid(HW / AQ, NH, BATCH);
        attn_fp16_kernel<<<grid, 256>>>(q, kbr, vbr, out);
    }
}

// round 11
// speedup vs baseline: 3.4137x; 1.1770x over previous
#include <cuda_runtime.h>
#include <cuda_fp16.h>
#include <cstdint>

// ---------------------------------------------------------------------------
// MobileMQA, fp16 dataflow: qkv conv1x1 (fp16 MMA, fused 3-in-1 launch) ->
// fused dw3x3s2+GN+SiLU (k&v in one launch) -> pw1x1 (fp16 MMA, k&v fused) ->
// GN+SiLU (fused) -> fp16 MMA flash attention.
// All intermediates stored fp16 (same mantissa as tf32; attention already
// consumed fp16). B=32, C=256, H=W=32, heads=8, Dh=32, groups=32.
// ---------------------------------------------------------------------------

#define BATCH 32
#define CH 256
#define HW 1024
#define HWD 256
#define NH 8
#define DH 32
#define GROUPS 32
#define CPG 8
#define EPS 1e-5f

__device__ float g_scratch[33554432];   // arena, used as __half[67108864]

// offsets in halves
#define OFF_Q     0
#define OFF_KFULL 8388608
#define OFF_VFULL 16777216
#define OFF_KDS   25165824
#define OFF_VDS   27262976
#define OFF_KBR   29360128
#define OFF_VBR   31457280

__device__ __forceinline__ float fast_exp2(float x) {
    float y;
    asm("ex2.approx.ftz.f32 %0, %1;" : "=f"(y) : "f"(x));
    return y;
}

__device__ __forceinline__ uint32_t pack2h(float a, float b) {
    __half2 h = __floats2half2_rn(a, b);
    return *reinterpret_cast<uint32_t*>(&h);
}

#define MMA_F16(acc, a0,a1,a2,a3, b0,b1)                                    \
    asm volatile(                                                           \
        "mma.sync.aligned.m16n8k16.row.col.f32.f16.f16.f32 "                \
        "{%0,%1,%2,%3}, {%4,%5,%6,%7}, {%8,%9}, {%0,%1,%2,%3};"             \
        : "+f"((acc)[0]), "+f"((acc)[1]), "+f"((acc)[2]), "+f"((acc)[3])    \
        : "r"(a0), "r"(a1), "r"(a2), "r"(a3), "r"(b0), "r"(b1))

// ---------------------------------------------------------------------------
// fp16 tensor-core GEMM, up to 3 weight sets in one launch.
// grid.y: (y>>1) selects set, (y&1) selects 128-row m-tile.
// Y[set][b] (fp16) = W[set] (256x256 fp32) * X[b] (256xN) + bias[set].
// Block 128x64, BK=32 (2 x k16 steps), 8 warps 4x2, warp tile 32x32.
// smem: sA half[128][40] ([m][k]), sB half[64][40] ([n][k], transposed).
// Fragment LDS bank-conflict-free (20g+tig bijective mod 32).
// ---------------------------------------------------------------------------
#define GK 256
#define GPAD 40

template<bool XH>
__global__ void __launch_bounds__(256, 2)
gemm_f16_kernel(const float* __restrict__ Wa, const float* __restrict__ Ba, __half* __restrict__ Ya,
                const float* __restrict__ Wb, const float* __restrict__ Bb, __half* __restrict__ Yb,
                const float* __restrict__ Wc, const float* __restrict__ Bc, __half* __restrict__ Yc,
                const void* __restrict__ Xa, const void* __restrict__ Xb2, const void* __restrict__ Xc,
                int N)
{
    const int which = blockIdx.y >> 1;
    const float* W    = which == 0 ? Wa : (which == 1 ? Wb : Wc);
    const float* bias = which == 0 ? Ba : (which == 1 ? Bb : Bc);
    __half* Y         = which == 0 ? Ya : (which == 1 ? Yb : Yc);
    const void* X     = which == 0 ? Xa : (which == 1 ? Xb2 : Xc);

    const int b  = blockIdx.z;
    const int m0 = (blockIdx.y & 1) * 128;
    const int n0 = blockIdx.x * 64;

    const float*  Xf = (const float*)X + (size_t)b * GK * N;
    const __half* Xh = (const __half*)X + (size_t)b * GK * N;
    __half* Yb_ = Y + (size_t)b * 256 * N;

    __shared__ __half sA[128 * GPAD];
    __shared__ __half sB[64 * GPAD];

    const int t    = threadIdx.x;
    const int wid  = t >> 5;
    const int lane = t & 31;
    const int wm   = wid & 3;
    const int wn   = wid >> 2;
    const int g    = lane >> 2;
    const int tig  = lane & 3;

    float acc[2][4][4];
#pragma unroll
    for (int mt = 0; mt < 2; mt++)
#pragma unroll
        for (int nt = 0; nt < 4; nt++)
#pragma unroll
            for (int i = 0; i < 4; i++) acc[mt][nt][i] = 0.f;

    for (int k0 = 0; k0 < GK; k0 += 32) {
        // ---- stage A (fp32 -> fp16): 128x32, float4 x4/thread ----
#pragma unroll
        for (int j = 0; j < 4; j++) {
            int i = t + j * 256;
            int m = i >> 3;
            int kq = i & 7;
            const float4 v = *reinterpret_cast<const float4*>(
                &W[(size_t)(m0 + m) * GK + k0 + kq * 4]);
            __half2* dst = reinterpret_cast<__half2*>(&sA[m * GPAD + kq * 4]);
            dst[0] = __floats2half2_rn(v.x, v.y);
            dst[1] = __floats2half2_rn(v.z, v.w);
        }
        // ---- stage B transposed [k][n] -> [n][k]: 32x64, 8/thread ----
#pragma unroll
        for (int j = 0; j < 8; j++) {
            int i = t + j * 256;
            int k = i >> 6;
            int n = i & 63;
            if (XH)
                sB[n * GPAD + k] = Xh[(size_t)(k0 + k) * N + n0 + n];
            else
                sB[n * GPAD + k] = __float2half(Xf[(size_t)(k0 + k) * N + n0 + n]);
        }
        __syncthreads();

#pragma unroll
        for (int ks = 0; ks < 2; ks++) {
            const int kk = ks * 16;
            uint32_t af[2][4];
#pragma unroll
            for (int mt = 0; mt < 2; mt++) {
                int r = wm * 32 + mt * 16 + g;
                af[mt][0] = *reinterpret_cast<const uint32_t*>(&sA[r * GPAD + kk + 2 * tig]);
                af[mt][1] = *reinterpret_cast<const uint32_t*>(&sA[(r + 8) * GPAD + kk + 2 * tig]);
                af[mt][2] = *reinterpret_cast<const uint32_t*>(&sA[r * GPAD + kk + 2 * tig + 8]);
                af[mt][3] = *reinterpret_cast<const uint32_t*>(&sA[(r + 8) * GPAD + kk + 2 * tig + 8]);
            }
#pragma unroll
            for (int nt = 0; nt < 4; nt++) {
                int n = wn * 32 + nt * 8 + g;
                uint32_t b0 = *reinterpret_cast<const uint32_t*>(&sB[n * GPAD + kk + 2 * tig]);
                uint32_t b1 = *reinterpret_cast<const uint32_t*>(&sB[n * GPAD + kk + 2 * tig + 8]);
#pragma unroll
                for (int mt = 0; mt < 2; mt++)
                    MMA_F16(acc[mt][nt], af[mt][0], af[mt][1], af[mt][2], af[mt][3], b0, b1);
            }
        }
        __syncthreads();
    }

#pragma unroll
    for (int mt = 0; mt < 2; mt++) {
        int r = m0 + wm * 32 + mt * 16 + g;
        float b0 = bias ? bias[r] : 0.f;
        float b1 = bias ? bias[r + 8] : 0.f;
#pragma unroll
        for (int nt = 0; nt < 4; nt++) {
            int c = n0 + wn * 32 + nt * 8 + tig * 2;
            *reinterpret_cast<__half2*>(&Yb_[(size_t)r * N + c]) =
                __floats2half2_rn(acc[mt][nt][0] + b0, acc[mt][nt][1] + b0);
            *reinterpret_cast<__half2*>(&Yb_[(size_t)(r + 8) * N + c]) =
                __floats2half2_rn(acc[mt][nt][2] + b1, acc[mt][nt][3] + b1);
        }
    }
}

// ---------------------------------------------------------------------------
// Fused depthwise 3x3 s2 + GroupNorm + SiLU, fp16 I/O, k&v via blockIdx.z.
// grid (GROUPS, BATCH, 2), 256 threads = one output pixel each.
// ---------------------------------------------------------------------------
__global__ void dwgn_silu_kernel(const __half* __restrict__ kin, const __half* __restrict__ vin,
                                 const float* __restrict__ kdw, const float* __restrict__ vdw,
                                 const float* __restrict__ ksc, const float* __restrict__ vsc,
                                 const float* __restrict__ kbi, const float* __restrict__ vbi,
                                 __half* __restrict__ kout, __half* __restrict__ vout)
{
    const int z  = blockIdx.z;
    const __half* in = z ? vin : kin;
    const float* dw  = z ? vdw : kdw;
    const float* scale = z ? vsc : ksc;
    const float* bias  = z ? vbi : kbi;
    __half* out = z ? vout : kout;

    const int gr = blockIdx.x;
    const int b  = blockIdx.y;
    const int p  = threadIdx.x;
    const int ox = p & 15;
    const int oy = p >> 4;

    float vals[CPG];
    float s = 0.f, s2 = 0.f;
#pragma unroll
    for (int c = 0; c < CPG; c++) {
        int ch = gr * CPG + c;
        const __half* ib = in + ((size_t)b * CH + ch) * HW;
        const float* wc = dw + ch * 9;
        float acc = 0.f;
#pragma unroll
        for (int ky = 0; ky < 3; ky++) {
            int iy = 2 * oy - 1 + ky;
            if ((unsigned)iy >= 32u) continue;
#pragma unroll
            for (int kx = 0; kx < 3; kx++) {
                int ix = 2 * ox - 1 + kx;
                if ((unsigned)ix >= 32u) continue;
                acc += __half2float(ib[iy * 32 + ix]) * wc[ky * 3 + kx];
            }
        }
        vals[c] = acc;
        s += acc; s2 += acc * acc;
    }

#pragma unroll
    for (int o = 16; o > 0; o >>= 1) {
        s  += __shfl_down_sync(0xffffffffu, s,  o);
        s2 += __shfl_down_sync(0xffffffffu, s2, o);
    }
    __shared__ float rs[8], rs2[8];
    __shared__ float mu_s, rstd_s;
    int warp = p >> 5, lane = p & 31;
    if (lane == 0) { rs[warp] = s; rs2[warp] = s2; }
    __syncthreads();
    if (p == 0) {
        float S = 0.f, S2 = 0.f;
#pragma unroll
        for (int w = 0; w < 8; w++) { S += rs[w]; S2 += rs2[w]; }
        float mu  = S * (1.f / (CPG * HWD));
        float var = S2 * (1.f / (CPG * HWD)) - mu * mu;
        mu_s = mu;
        rstd_s = rsqrtf(var + EPS);
    }
    __syncthreads();
    float mu = mu_s, rstd = rstd_s;

#pragma unroll
    for (int c = 0; c < CPG; c++) {
        int ch = gr * CPG + c;
        float y = (vals[c] - mu) * rstd * scale[ch] + bias[ch];
        y = y / (1.f + __expf(-y));
        out[((size_t)b * CH + ch) * HWD + p] = __float2half(y);
    }
}

// ---------------------------------------------------------------------------
// GroupNorm + SiLU, fp16 in-place, k&v via blockIdx.z.
// ---------------------------------------------------------------------------
__global__ void gn_silu_kernel(__half* __restrict__ kx, __half* __restrict__ vx,
                               const float* __restrict__ ksc, const float* __restrict__ vsc,
                               const float* __restrict__ kbi, const float* __restrict__ vbi)
{
    const int z = blockIdx.z;
    __half* x = z ? vx : kx;
    const float* scale = z ? vsc : ksc;
    const float* bias  = z ? vbi : kbi;

    const int g = blockIdx.x;
    const int b = blockIdx.y;
    __half* base = x + ((size_t)b * CH + g * CPG) * HWD;
    const int p = threadIdx.x;

    float vals[CPG];
    float s = 0.f, s2 = 0.f;
#pragma unroll
    for (int c = 0; c < CPG; c++) {
        float v = __half2float(base[c * HWD + p]);
        vals[c] = v;
        s += v; s2 += v * v;
    }

#pragma unroll
    for (int o = 16; o > 0; o >>= 1) {
        s  += __shfl_down_sync(0xffffffffu, s,  o);
        s2 += __shfl_down_sync(0xffffffffu, s2, o);
    }
    __shared__ float rs[8], rs2[8];
    __shared__ float mu_s, rstd_s;
    int warp = p >> 5, lane = p & 31;
    if (lane == 0) { rs[warp] = s; rs2[warp] = s2; }
    __syncthreads();
    if (p == 0) {
        float S = 0.f, S2 = 0.f;
#pragma unroll
        for (int w = 0; w < 8; w++) { S += rs[w]; S2 += rs2[w]; }
        float mu  = S * (1.f / (CPG * HWD));
        float var = S2 * (1.f / (CPG * HWD)) - mu * mu;
        mu_s = mu;
        rstd_s = rsqrtf(var + EPS);
    }
    __syncthreads();
    float mu = mu_s, rstd = rstd_s;

#pragma unroll
    for (int c = 0; c < CPG; c++) {
        int ch = g * CPG + c;
        float y = (vals[c] - mu) * rstd * scale[ch] + bias[ch];
        y = y / (1.f + __expf(-y));
        base[c * HWD + p] = __float2half(y);
    }
}

// ---------------------------------------------------------------------------
// fp16 tensor-core flash attention (inputs already fp16 -> pure-copy staging;
// softmax scale applied post-MMA). Block = (b,h) x 128 queries, M=256 KV.
// ---------------------------------------------------------------------------
#define AQ 128
#define AM 256
#define QPAD 40
#define VPAD 264
#define SMEM_HALVES (AQ*QPAD + AM*QPAD + DH*VPAD)   // 23808 halves = 47616 B

__global__ void __launch_bounds__(256, 2)
attn_fp16_kernel(const __half* __restrict__ q,
                 const __half* __restrict__ k,
                 const __half* __restrict__ v,
                 float* __restrict__ out)
{
    __shared__ __align__(16) __half smem[SMEM_HALVES];
    __half* sQ = smem;
    __half* sK = smem + AQ * QPAD;
    __half* sV = smem + AQ * QPAD + AM * QPAD;
    float* sO = reinterpret_cast<float*>(smem);

    const int b  = blockIdx.z;
    const int h  = blockIdx.y;
    const int n0 = blockIdx.x * AQ;

    const __half* qb = q + ((size_t)b * CH + h * DH) * HW;
    const __half* kb = k + ((size_t)b * CH + h * DH) * HWD;
    const __half* vb = v + ((size_t)b * CH + h * DH) * HWD;
    float* ob = out + ((size_t)b * CH + h * DH) * HW;

    const int t    = threadIdx.x;
    const int w    = t >> 5;
    const int lane = t & 31;
    const int g    = lane >> 2;
    const int tig  = lane & 3;
    const int r0   = w * 16;

    const float qs = 0.17677669529663687f * 1.4426950408889634f; // /sqrt(32)*log2e

    for (int i = t; i < AQ * DH; i += 256) {
        int d = i >> 7, n = i & 127;
        sQ[n * QPAD + d] = qb[d * HW + n0 + n];
    }
    for (int i = t; i < AM * DH; i += 256) {
        int d = i >> 8, m = i & 255;
        sK[m * QPAD + d] = kb[d * HWD + m];
        sV[d * VPAD + m] = vb[d * HWD + m];
    }
    __syncthreads();

    float o[4][4];
#pragma unroll
    for (int dt = 0; dt < 4; dt++)
#pragma unroll
        for (int i = 0; i < 4; i++) o[dt][i] = 0.f;
    float mx0 = -1e30f, mx1 = -1e30f, sum0 = 0.f, sum1 = 0.f;

#pragma unroll
    for (int chunk = 0; chunk < 2; chunk++) {
        const int c0 = chunk * 128;

        float s[16][4];
#pragma unroll
        for (int nt = 0; nt < 16; nt++)
#pragma unroll
            for (int i = 0; i < 4; i++) s[nt][i] = 0.f;

#pragma unroll
        for (int ks = 0; ks < 2; ks++) {
            const int kk = ks * 16;
            uint32_t a0 = *reinterpret_cast<const uint32_t*>(&sQ[(r0 + g) * QPAD + kk + 2 * tig]);
            uint32_t a1 = *reinterpret_cast<const uint32_t*>(&sQ[(r0 + g + 8) * QPAD + kk + 2 * tig]);
            uint32_t a2 = *reinterpret_cast<const uint32_t*>(&sQ[(r0 + g) * QPAD + kk + 2 * tig + 8]);
            uint32_t a3 = *reinterpret_cast<const uint32_t*>(&sQ[(r0 + g + 8) * QPAD + kk + 2 * tig + 8]);
#pragma unroll
            for (int nt = 0; nt < 16; nt++) {
                int m = c0 + nt * 8 + g;
                uint32_t b0 = *reinterpret_cast<const uint32_t*>(&sK[m * QPAD + kk + 2 * tig]);
                uint32_t b1 = *reinterpret_cast<const uint32_t*>(&sK[m * QPAD + kk + 2 * tig + 8]);
                MMA_F16(s[nt], a0, a1, a2, a3, b0, b1);
            }
        }

        // apply softmax scale (folded with log2e)
#pragma unroll
        for (int nt = 0; nt < 16; nt++)
#pragma unroll
            for (int i = 0; i < 4; i++) s[nt][i] *= qs;

        float cm0 = -1e30f, cm1 = -1e30f;
#pragma unroll
        for (int nt = 0; nt < 16; nt++) {
            cm0 = fmaxf(cm0, fmaxf(s[nt][0], s[nt][1]));
            cm1 = fmaxf(cm1, fmaxf(s[nt][2], s[nt][3]));
        }
        cm0 = fmaxf(cm0, __shfl_xor_sync(0xffffffffu, cm0, 1));
        cm0 = fmaxf(cm0, __shfl_xor_sync(0xffffffffu, cm0, 2));
        cm1 = fmaxf(cm1, __shfl_xor_sync(0xffffffffu, cm1, 1));
        cm1 = fmaxf(cm1, __shfl_xor_sync(0xffffffffu, cm1, 2));

        float nm0 = fmaxf(mx0, cm0);
        float nm1 = fmaxf(mx1, cm1);
        float f0 = fast_exp2(mx0 - nm0);
        float f1 = fast_exp2(mx1 - nm1);
        sum0 *= f0; sum1 *= f1;
#pragma unroll
        for (int dt = 0; dt < 4; dt++) {
            o[dt][0] *= f0; o[dt][1] *= f0;
            o[dt][2] *= f1; o[dt][3] *= f1;
        }
        mx0 = nm0; mx1 = nm1;

#pragma unroll
        for (int mc = 0; mc < 8; mc++) {
            float p00 = fast_exp2(s[2*mc][0] - mx0);
            float p01 = fast_exp2(s[2*mc][1] - mx0);
            float p02 = fast_exp2(s[2*mc][2] - mx1);
            float p03 = fast_exp2(s[2*mc][3] - mx1);
            float p10 = fast_exp2(s[2*mc+1][0] - mx0);
            float p11 = fast_exp2(s[2*mc+1][1] - mx0);
            float p12 = fast_exp2(s[2*mc+1][2] - mx1);
            float p13 = fast_exp2(s[2*mc+1][3] - mx1);
            sum0 += p00 + p01 + p10 + p11;
            sum1 += p02 + p03 + p12 + p13;
            uint32_t a0 = pack2h(p00, p01);
            uint32_t a1 = pack2h(p02, p03);
            uint32_t a2 = pack2h(p10, p11);
            uint32_t a3 = pack2h(p12, p13);
            const int mbase = c0 + mc * 16 + 2 * tig;
#pragma unroll
            for (int dt = 0; dt < 4; dt++) {
                int dd = dt * 8 + g;
                uint32_t b0 = *reinterpret_cast<const uint32_t*>(&sV[dd * VPAD + mbase]);
                uint32_t b1 = *reinterpret_cast<const uint32_t*>(&sV[dd * VPAD + mbase + 8]);
                MMA_F16(o[dt], a0, a1, a2, a3, b0, b1);
            }
        }
    }

    sum0 += __shfl_xor_sync(0xffffffffu, sum0, 1);
    sum0 += __shfl_xor_sync(0xffffffffu, sum0, 2);
    sum1 += __shfl_xor_sync(0xffffffffu, sum1, 1);
    sum1 += __shfl_xor_sync(0xffffffffu, sum1, 2);
    float inv0 = 1.f / sum0;
    float inv1 = 1.f / sum1;

    __syncthreads();

#pragma unroll
    for (int dt = 0; dt < 4; dt++) {
        int c = dt * 8 + tig * 2;
        sO[(r0 + g) * 33 + c]     = o[dt][0] * inv0;
        sO[(r0 + g) * 33 + c + 1] = o[dt][1] * inv0;
        sO[(r0 + g + 8) * 33 + c]     = o[dt][2] * inv1;
        sO[(r0 + g + 8) * 33 + c + 1] = o[dt][3] * inv1;
    }
    __syncthreads();

    for (int i = t; i < AQ * DH; i += 256) {
        int d = i >> 7, n = i & 127;
        ob[d * HW + n0 + n] = sO[n * 33 + d];
    }
}

// ---------------------------------------------------------------------------
// Host launcher
// ---------------------------------------------------------------------------
extern "C" void kernel_launch(void* const* d_in, const int* in_sizes, int n_in,
                              void* d_out, int out_size)
{
    const float* x      = (const float*)d_in[0];
    const float* wq     = (const float*)d_in[1];
    const float* bq     = (const float*)d_in[2];
    const float* wk     = (const float*)d_in[3];
    const float* bk     = (const float*)d_in[4];
    const float* wv     = (const float*)d_in[5];
    const float* bv     = (const float*)d_in[6];
    const float* k_dw   = (const float*)d_in[7];
    const float* k_gn1s = (const float*)d_in[8];
    const float* k_gn1b = (const float*)d_in[9];
    const float* k_pw   = (const float*)d_in[10];
    const float* k_gn2s = (const float*)d_in[11];
    const float* k_gn2b = (const float*)d_in[12];
    const float* v_dw   = (const float*)d_in[13];
    const float* v_gn1s = (const float*)d_in[14];
    const float* v_gn1b = (const float*)d_in[15];
    const float* v_pw   = (const float*)d_in[16];
    const float* v_gn2s = (const float*)d_in[17];
    const float* v_gn2b = (const float*)d_in[18];
    float* out = (float*)d_out;

    float* basef = nullptr;
    cudaGetSymbolAddress((void**)&basef, g_scratch);
    __half* base = (__half*)basef;
    __half* q     = base + OFF_Q;
    __half* kfull = base + OFF_KFULL;
    __half* vfull = base + OFF_VFULL;
    __half* kds   = base + OFF_KDS;
    __half* vds   = base + OFF_VDS;
    __half* kbr   = base + OFF_KBR;
    __half* vbr   = base + OFF_VBR;

    // 1) q/k/v pointwise convs fused in one launch (fp16 MMA, X fp32)
    {
        dim3 grid(HW / 64, 6, BATCH);
        gemm_f16_kernel<false><<<grid, 256>>>(
            wq, bq, q,  wk, bk, kfull,  wv, bv, vfull,
            x, x, x, HW);
    }

    // 2) fused depthwise s2 + GN1 + SiLU (k & v)
    {
        dim3 grid(GROUPS, BATCH, 2);
        dwgn_silu_kernel<<<grid, HWD>>>(kfull, vfull, k_dw, v_dw,
                                        k_gn1s, v_gn1s, k_gn1b, v_gn1b,
                                        kds, vds);
    }

    // 3) pointwise convs (no bias), k & v fused (fp16 MMA, X fp16)
    {
        dim3 grid(HWD / 64, 4, BATCH);
        gemm_f16_kernel<true><<<grid, 256>>>(
            k_pw, nullptr, kbr,  v_pw, nullptr, vbr,  k_pw, nullptr, kbr,
            kds, vds, kds, HWD);
    }

    // 4) GN2 + SiLU (k & v, in-place)
    {
        dim3 grid(GROUPS, BATCH, 2);
        gn_silu_kernel<<<grid, HWD>>>(kbr, vbr, k_gn2s, v_gn2s, k_gn2b, v_gn2b);
    }

    // 5) attention -> output (B,C,H,W) fp32
    {
        dim3 grid(HW / AQ, NH, BATCH);
        attn_fp16_kernel<<<grid, 256>>>(q, kbr, vbr, out);
    }
}

// round 16
// speedup vs baseline: 4.0372x; 1.1826x over previous
#include <cuda_runtime.h>
#include <cuda_fp16.h>
#include <cstdint>

// ---------------------------------------------------------------------------
// MobileMQA, all-fp16 dataflow with pre-converted operands:
// prep (W->fp16, x->x^T fp16) -> qkv conv1x1 (fp16 MMA 128x128 tiles, 3-in-1)
// -> fused dw3x3s2+GN+SiLU (k&v, outputs [n][k]) -> pw1x1 (fp16 MMA, k&v)
// -> GN+SiLU (k&v) -> fp16 MMA flash attention.
// B=32, C=256, H=W=32, heads=8, Dh=32, groups=32.
// ---------------------------------------------------------------------------

#define BATCH 32
#define CH 256
#define HW 1024
#define HWD 256
#define NH 8
#define DH 32
#define GROUPS 32
#define CPG 8
#define EPS 1e-5f

__device__ float g_scratch[33554432];   // arena, used as __half[67108864]

// offsets in halves
#define OFF_Q     0
#define OFF_KFULL 8388608
#define OFF_VFULL 16777216
#define OFF_KDS   25165824          // [b][n][k] layout
#define OFF_VDS   27262976          // [b][n][k] layout
#define OFF_KBR   29360128
#define OFF_VBR   31457280
#define OFF_XH    33554432          // x^T: [b][n=1024][k=256] fp16
#define OFF_WQH   41943040
#define OFF_WKH   42008576
#define OFF_WVH   42074112
#define OFF_KPWH  42139648
#define OFF_VPWH  42205184

__device__ __forceinline__ float fast_exp2(float x) {
    float y;
    asm("ex2.approx.ftz.f32 %0, %1;" : "=f"(y) : "f"(x));
    return y;
}

__device__ __forceinline__ uint32_t pack2h(float a, float b) {
    __half2 h = __floats2half2_rn(a, b);
    return *reinterpret_cast<uint32_t*>(&h);
}

#define MMA_F16(acc, a0,a1,a2,a3, b0,b1)                                    \
    asm volatile(                                                           \
        "mma.sync.aligned.m16n8k16.row.col.f32.f16.f16.f32 "                \
        "{%0,%1,%2,%3}, {%4,%5,%6,%7}, {%8,%9}, {%0,%1,%2,%3};"             \
        : "+f"((acc)[0]), "+f"((acc)[1]), "+f"((acc)[2]), "+f"((acc)[3])    \
        : "r"(a0), "r"(a1), "r"(a2), "r"(a3), "r"(b0), "r"(b1))

// ---------------------------------------------------------------------------
// Prep 1: convert 5 weight matrices (256x256 fp32) to fp16.
// grid (64, 5), 256 threads, 4 elems/thread.
// ---------------------------------------------------------------------------
__global__ void wconv_kernel(const float* __restrict__ w0, const float* __restrict__ w1,
                             const float* __restrict__ w2, const float* __restrict__ w3,
                             const float* __restrict__ w4,
                             __half* __restrict__ o0, __half* __restrict__ o1,
                             __half* __restrict__ o2, __half* __restrict__ o3,
                             __half* __restrict__ o4)
{
    const int s = blockIdx.y;
    const float* w = s == 0 ? w0 : s == 1 ? w1 : s == 2 ? w2 : s == 3 ? w3 : w4;
    __half* o      = s == 0 ? o0 : s == 1 ? o1 : s == 2 ? o2 : s == 3 ? o3 : o4;
    int i = (blockIdx.x * 256 + threadIdx.x) * 4;
    float4 v = *reinterpret_cast<const float4*>(&w[i]);
    *reinterpret_cast<__half2*>(&o[i])     = __floats2half2_rn(v.x, v.y);
    *reinterpret_cast<__half2*>(&o[i + 2]) = __floats2half2_rn(v.z, v.w);
}

// ---------------------------------------------------------------------------
// Prep 2: transpose+convert x (B,256,1024 fp32) -> xh (B,1024,256 fp16).
// grid (HW/32, CH/32, BATCH), block (32,8).
// ---------------------------------------------------------------------------
__global__ void xpose_kernel(const float* __restrict__ x, __half* __restrict__ xh)
{
    __shared__ __half tile[32][33];
    const int n0 = blockIdx.x * 32;
    const int k0 = blockIdx.y * 32;
    const int b  = blockIdx.z;
    const float* xb = x + (size_t)b * CH * HW;
    __half* xo = xh + (size_t)b * HW * CH;

#pragma unroll
    for (int i = threadIdx.y; i < 32; i += 8)
        tile[i][threadIdx.x] = __float2half(xb[(size_t)(k0 + i) * HW + n0 + threadIdx.x]);
    __syncthreads();
#pragma unroll
    for (int i = threadIdx.y; i < 32; i += 8)
        xo[(size_t)(n0 + i) * CH + k0 + threadIdx.x] = tile[threadIdx.x][i];
}

// ---------------------------------------------------------------------------
// fp16 tensor-core GEMM, up to 3 weight sets per launch.
// Y[set][b] (fp16, [m][n]) = W[set] (fp16 [m][k]) * X[b] (fp16 [n][k], i.e.
// pre-transposed) + bias[set] (fp32).
// grid.y: (y>>1) selects set, (y&1) selects 128-row m-tile.
// Block tile 128x128, BK=32, 256 threads (8 warps 4x2), warp tile 32x64.
// smem: sA half[128][40], sB half[128][40]; both staged with uint4 loads.
// Fragment LDS bank-conflict-free (20g+tig bijective mod 32).
// ---------------------------------------------------------------------------
#define GK 256
#define GPAD 40

__global__ void __launch_bounds__(256, 2)
gemm_f16_kernel(const __half* __restrict__ Wa, const float* __restrict__ Ba, __half* __restrict__ Ya,
                const __half* __restrict__ Wb, const float* __restrict__ Bb, __half* __restrict__ Yb,
                const __half* __restrict__ Wc, const float* __restrict__ Bc, __half* __restrict__ Yc,
                const __half* __restrict__ Xa, const __half* __restrict__ Xb2, const __half* __restrict__ Xc,
                int N)
{
    const int which = blockIdx.y >> 1;
    const __half* W   = which == 0 ? Wa : (which == 1 ? Wb : Wc);
    const float* bias = which == 0 ? Ba : (which == 1 ? Bb : Bc);
    __half* Y         = which == 0 ? Ya : (which == 1 ? Yb : Yc);
    const __half* X   = which == 0 ? Xa : (which == 1 ? Xb2 : Xc);

    const int b  = blockIdx.z;
    const int m0 = (blockIdx.y & 1) * 128;
    const int n0 = blockIdx.x * 128;

    const __half* Xb_ = X + (size_t)b * N * GK;   // [n][k]
    __half* Yo = Y + (size_t)b * 256 * N;

    __shared__ __half sA[128 * GPAD];
    __shared__ __half sB[128 * GPAD];

    const int t    = threadIdx.x;
    const int wid  = t >> 5;
    const int lane = t & 31;
    const int wm   = wid & 3;
    const int wn   = wid >> 2;
    const int g    = lane >> 2;
    const int tig  = lane & 3;

    float acc[2][8][4];
#pragma unroll
    for (int mt = 0; mt < 2; mt++)
#pragma unroll
        for (int nt = 0; nt < 8; nt++)
#pragma unroll
            for (int i = 0; i < 4; i++) acc[mt][nt][i] = 0.f;

    for (int k0 = 0; k0 < GK; k0 += 32) {
        // stage A and B: each 128 rows x 32 halves, uint4 (8 halves) x2/thread
#pragma unroll
        for (int j = 0; j < 2; j++) {
            int i = t + j * 256;
            int m = i >> 2;
            int kq = i & 3;
            *reinterpret_cast<uint4*>(&sA[m * GPAD + kq * 8]) =
                *reinterpret_cast<const uint4*>(&W[(size_t)(m0 + m) * GK + k0 + kq * 8]);
            *reinterpret_cast<uint4*>(&sB[m * GPAD + kq * 8]) =
                *reinterpret_cast<const uint4*>(&Xb_[(size_t)(n0 + m) * GK + k0 + kq * 8]);
        }
        __syncthreads();

#pragma unroll
        for (int ks = 0; ks < 2; ks++) {
            const int kk = ks * 16;
            uint32_t af[2][4];
#pragma unroll
            for (int mt = 0; mt < 2; mt++) {
                int r = wm * 32 + mt * 16 + g;
                af[mt][0] = *reinterpret_cast<const uint32_t*>(&sA[r * GPAD + kk + 2 * tig]);
                af[mt][1] = *reinterpret_cast<const uint32_t*>(&sA[(r + 8) * GPAD + kk + 2 * tig]);
                af[mt][2] = *reinterpret_cast<const uint32_t*>(&sA[r * GPAD + kk + 2 * tig + 8]);
                af[mt][3] = *reinterpret_cast<const uint32_t*>(&sA[(r + 8) * GPAD + kk + 2 * tig + 8]);
            }
#pragma unroll
            for (int nt = 0; nt < 8; nt++) {
                int n = wn * 64 + nt * 8 + g;
                uint32_t b0 = *reinterpret_cast<const uint32_t*>(&sB[n * GPAD + kk + 2 * tig]);
                uint32_t b1 = *reinterpret_cast<const uint32_t*>(&sB[n * GPAD + kk + 2 * tig + 8]);
#pragma unroll
                for (int mt = 0; mt < 2; mt++)
                    MMA_F16(acc[mt][nt], af[mt][0], af[mt][1], af[mt][2], af[mt][3], b0, b1);
            }
        }
        __syncthreads();
    }

#pragma unroll
    for (int mt = 0; mt < 2; mt++) {
        int r = m0 + wm * 32 + mt * 16 + g;
        float b0 = bias ? bias[r] : 0.f;
        float b1 = bias ? bias[r + 8] : 0.f;
#pragma unroll
        for (int nt = 0; nt < 8; nt++) {
            int c = n0 + wn * 64 + nt * 8 + tig * 2;
            *reinterpret_cast<__half2*>(&Yo[(size_t)r * N + c]) =
                __floats2half2_rn(acc[mt][nt][0] + b0, acc[mt][nt][1] + b0);
            *reinterpret_cast<__half2*>(&Yo[(size_t)(r + 8) * N + c]) =
                __floats2half2_rn(acc[mt][nt][2] + b1, acc[mt][nt][3] + b1);
        }
    }
}

// ---------------------------------------------------------------------------
// Fused depthwise 3x3 s2 + GroupNorm + SiLU, fp16 I/O, k&v via blockIdx.z.
// Output written TRANSPOSED per batch: [n=pixel][k=channel] (GEMM B format).
// grid (GROUPS, BATCH, 2), 256 threads = one output pixel each.
// ---------------------------------------------------------------------------
__global__ void dwgn_silu_kernel(const __half* __restrict__ kin, const __half* __restrict__ vin,
                                 const float* __restrict__ kdw, const float* __restrict__ vdw,
                                 const float* __restrict__ ksc, const float* __restrict__ vsc,
                                 const float* __restrict__ kbi, const float* __restrict__ vbi,
                                 __half* __restrict__ kout, __half* __restrict__ vout)
{
    const int z  = blockIdx.z;
    const __half* in = z ? vin : kin;
    const float* dw  = z ? vdw : kdw;
    const float* scale = z ? vsc : ksc;
    const float* bias  = z ? vbi : kbi;
    __half* out = z ? vout : kout;

    const int gr = blockIdx.x;
    const int b  = blockIdx.y;
    const int p  = threadIdx.x;
    const int ox = p & 15;
    const int oy = p >> 4;

    float vals[CPG];
    float s = 0.f, s2 = 0.f;
#pragma unroll
    for (int c = 0; c < CPG; c++) {
        int ch = gr * CPG + c;
        const __half* ib = in + ((size_t)b * CH + ch) * HW;
        const float* wc = dw + ch * 9;
        float acc = 0.f;
#pragma unroll
        for (int ky = 0; ky < 3; ky++) {
            int iy = 2 * oy - 1 + ky;
            if ((unsigned)iy >= 32u) continue;
#pragma unroll
            for (int kx = 0; kx < 3; kx++) {
                int ix = 2 * ox - 1 + kx;
                if ((unsigned)ix >= 32u) continue;
                acc += __half2float(ib[iy * 32 + ix]) * wc[ky * 3 + kx];
            }
        }
        vals[c] = acc;
        s += acc; s2 += acc * acc;
    }

#pragma unroll
    for (int o = 16; o > 0; o >>= 1) {
        s  += __shfl_down_sync(0xffffffffu, s,  o);
        s2 += __shfl_down_sync(0xffffffffu, s2, o);
    }
    __shared__ float rs[8], rs2[8];
    __shared__ float mu_s, rstd_s;
    int warp = p >> 5, lane = p & 31;
    if (lane == 0) { rs[warp] = s; rs2[warp] = s2; }
    __syncthreads();
    if (p == 0) {
        float S = 0.f, S2 = 0.f;
#pragma unroll
        for (int w = 0; w < 8; w++) { S += rs[w]; S2 += rs2[w]; }
        float mu  = S * (1.f / (CPG * HWD));
        float var = S2 * (1.f / (CPG * HWD)) - mu * mu;
        mu_s = mu;
        rstd_s = rsqrtf(var + EPS);
    }
    __syncthreads();
    float mu = mu_s, rstd = rstd_s;

    // transposed store: out[b][pixel p][channel ch], 8 consecutive channels
    __half hv[CPG];
#pragma unroll
    for (int c = 0; c < CPG; c++) {
        int ch = gr * CPG + c;
        float y = (vals[c] - mu) * rstd * scale[ch] + bias[ch];
        y = y / (1.f + __expf(-y));
        hv[c] = __float2half(y);
    }
    *reinterpret_cast<uint4*>(&out[((size_t)b * HWD + p) * CH + gr * CPG]) =
        *reinterpret_cast<uint4*>(hv);
}

// ---------------------------------------------------------------------------
// GroupNorm + SiLU, fp16 in-place ([ch][pixel] layout), k&v via blockIdx.z.
// ---------------------------------------------------------------------------
__global__ void gn_silu_kernel(__half* __restrict__ kx, __half* __restrict__ vx,
                               const float* __restrict__ ksc, const float* __restrict__ vsc,
                               const float* __restrict__ kbi, const float* __restrict__ vbi)
{
    const int z = blockIdx.z;
    __half* x = z ? vx : kx;
    const float* scale = z ? vsc : ksc;
    const float* bias  = z ? vbi : kbi;

    const int g = blockIdx.x;
    const int b = blockIdx.y;
    __half* base = x + ((size_t)b * CH + g * CPG) * HWD;
    const int p = threadIdx.x;

    float vals[CPG];
    float s = 0.f, s2 = 0.f;
#pragma unroll
    for (int c = 0; c < CPG; c++) {
        float v = __half2float(base[c * HWD + p]);
        vals[c] = v;
        s += v; s2 += v * v;
    }

#pragma unroll
    for (int o = 16; o > 0; o >>= 1) {
        s  += __shfl_down_sync(0xffffffffu, s,  o);
        s2 += __shfl_down_sync(0xffffffffu, s2, o);
    }
    __shared__ float rs[8], rs2[8];
    __shared__ float mu_s, rstd_s;
    int warp = p >> 5, lane = p & 31;
    if (lane == 0) { rs[warp] = s; rs2[warp] = s2; }
    __syncthreads();
    if (p == 0) {
        float S = 0.f, S2 = 0.f;
#pragma unroll
        for (int w = 0; w < 8; w++) { S += rs[w]; S2 += rs2[w]; }
        float mu  = S * (1.f / (CPG * HWD));
        float var = S2 * (1.f / (CPG * HWD)) - mu * mu;
        mu_s = mu;
        rstd_s = rsqrtf(var + EPS);
    }
    __syncthreads();
    float mu = mu_s, rstd = rstd_s;

#pragma unroll
    for (int c = 0; c < CPG; c++) {
        int ch = g * CPG + c;
        float y = (vals[c] - mu) * rstd * scale[ch] + bias[ch];
        y = y / (1.f + __expf(-y));
        base[c * HWD + p] = __float2half(y);
    }
}

// ---------------------------------------------------------------------------
// fp16 tensor-core flash attention. Block = (b,h) x 128 queries, M=256 KV.
// ---------------------------------------------------------------------------
#define AQ 128
#define AM 256
#define QPAD 40
#define VPAD 264
#define SMEM_HALVES (AQ*QPAD + AM*QPAD + DH*VPAD)

__global__ void __launch_bounds__(256, 2)
attn_fp16_kernel(const __half* __restrict__ q,
                 const __half* __restrict__ k,
                 const __half* __restrict__ v,
                 float* __restrict__ out)
{
    __shared__ __align__(16) __half smem[SMEM_HALVES];
    __half* sQ = smem;
    __half* sK = smem + AQ * QPAD;
    __half* sV = smem + AQ * QPAD + AM * QPAD;
    float* sO = reinterpret_cast<float*>(smem);

    const int b  = blockIdx.z;
    const int h  = blockIdx.y;
    const int n0 = blockIdx.x * AQ;

    const __half* qb = q + ((size_t)b * CH + h * DH) * HW;
    const __half* kb = k + ((size_t)b * CH + h * DH) * HWD;
    const __half* vb = v + ((size_t)b * CH + h * DH) * HWD;
    float* ob = out + ((size_t)b * CH + h * DH) * HW;

    const int t    = threadIdx.x;
    const int w    = t >> 5;
    const int lane = t & 31;
    const int g    = lane >> 2;
    const int tig  = lane & 3;
    const int r0   = w * 16;

    const float qs = 0.17677669529663687f * 1.4426950408889634f;

    for (int i = t; i < AQ * DH; i += 256) {
        int d = i >> 7, n = i & 127;
        sQ[n * QPAD + d] = qb[d * HW + n0 + n];
    }
    for (int i = t; i < AM * DH; i += 256) {
        int d = i >> 8, m = i & 255;
        sK[m * QPAD + d] = kb[d * HWD + m];
        sV[d * VPAD + m] = vb[d * HWD + m];
    }
    __syncthreads();

    float o[4][4];
#pragma unroll
    for (int dt = 0; dt < 4; dt++)
#pragma unroll
        for (int i = 0; i < 4; i++) o[dt][i] = 0.f;
    float mx0 = -1e30f, mx1 = -1e30f, sum0 = 0.f, sum1 = 0.f;

#pragma unroll
    for (int chunk = 0; chunk < 2; chunk++) {
        const int c0 = chunk * 128;

        float s[16][4];
#pragma unroll
        for (int nt = 0; nt < 16; nt++)
#pragma unroll
            for (int i = 0; i < 4; i++) s[nt][i] = 0.f;

#pragma unroll
        for (int ks = 0; ks < 2; ks++) {
            const int kk = ks * 16;
            uint32_t a0 = *reinterpret_cast<const uint32_t*>(&sQ[(r0 + g) * QPAD + kk + 2 * tig]);
            uint32_t a1 = *reinterpret_cast<const uint32_t*>(&sQ[(r0 + g + 8) * QPAD + kk + 2 * tig]);
            uint32_t a2 = *reinterpret_cast<const uint32_t*>(&sQ[(r0 + g) * QPAD + kk + 2 * tig + 8]);
            uint32_t a3 = *reinterpret_cast<const uint32_t*>(&sQ[(r0 + g + 8) * QPAD + kk + 2 * tig + 8]);
#pragma unroll
            for (int nt = 0; nt < 16; nt++) {
                int m = c0 + nt * 8 + g;
                uint32_t b0 = *reinterpret_cast<const uint32_t*>(&sK[m * QPAD + kk + 2 * tig]);
                uint32_t b1 = *reinterpret_cast<const uint32_t*>(&sK[m * QPAD + kk + 2 * tig + 8]);
                MMA_F16(s[nt], a0, a1, a2, a3, b0, b1);
            }
        }

#pragma unroll
        for (int nt = 0; nt < 16; nt++)
#pragma unroll
            for (int i = 0; i < 4; i++) s[nt][i] *= qs;

        float cm0 = -1e30f, cm1 = -1e30f;
#pragma unroll
        for (int nt = 0; nt < 16; nt++) {
            cm0 = fmaxf(cm0, fmaxf(s[nt][0], s[nt][1]));
            cm1 = fmaxf(cm1, fmaxf(s[nt][2], s[nt][3]));
        }
        cm0 = fmaxf(cm0, __shfl_xor_sync(0xffffffffu, cm0, 1));
        cm0 = fmaxf(cm0, __shfl_xor_sync(0xffffffffu, cm0, 2));
        cm1 = fmaxf(cm1, __shfl_xor_sync(0xffffffffu, cm1, 1));
        cm1 = fmaxf(cm1, __shfl_xor_sync(0xffffffffu, cm1, 2));

        float nm0 = fmaxf(mx0, cm0);
        float nm1 = fmaxf(mx1, cm1);
        float f0 = fast_exp2(mx0 - nm0);
        float f1 = fast_exp2(mx1 - nm1);
        sum0 *= f0; sum1 *= f1;
#pragma unroll
        for (int dt = 0; dt < 4; dt++) {
            o[dt][0] *= f0; o[dt][1] *= f0;
            o[dt][2] *= f1; o[dt][3] *= f1;
        }
        mx0 = nm0; mx1 = nm1;

#pragma unroll
        for (int mc = 0; mc < 8; mc++) {
            float p00 = fast_exp2(s[2*mc][0] - mx0);
            float p01 = fast_exp2(s[2*mc][1] - mx0);
            float p02 = fast_exp2(s[2*mc][2] - mx1);
            float p03 = fast_exp2(s[2*mc][3] - mx1);
            float p10 = fast_exp2(s[2*mc+1][0] - mx0);
            float p11 = fast_exp2(s[2*mc+1][1] - mx0);
            float p12 = fast_exp2(s[2*mc+1][2] - mx1);
            float p13 = fast_exp2(s[2*mc+1][3] - mx1);
            sum0 += p00 + p01 + p10 + p11;
            sum1 += p02 + p03 + p12 + p13;
            uint32_t a0 = pack2h(p00, p01);
            uint32_t a1 = pack2h(p02, p03);
            uint32_t a2 = pack2h(p10, p11);
            uint32_t a3 = pack2h(p12, p13);
            const int mbase = c0 + mc * 16 + 2 * tig;
#pragma unroll
            for (int dt = 0; dt < 4; dt++) {
                int dd = dt * 8 + g;
                uint32_t b0 = *reinterpret_cast<const uint32_t*>(&sV[dd * VPAD + mbase]);
                uint32_t b1 = *reinterpret_cast<const uint32_t*>(&sV[dd * VPAD + mbase + 8]);
                MMA_F16(o[dt], a0, a1, a2, a3, b0, b1);
            }
        }
    }

    sum0 += __shfl_xor_sync(0xffffffffu, sum0, 1);
    sum0 += __shfl_xor_sync(0xffffffffu, sum0, 2);
    sum1 += __shfl_xor_sync(0xffffffffu, sum1, 1);
    sum1 += __shfl_xor_sync(0xffffffffu, sum1, 2);
    float inv0 = 1.f / sum0;
    float inv1 = 1.f / sum1;

    __syncthreads();

#pragma unroll
    for (int dt = 0; dt < 4; dt++) {
        int c = dt * 8 + tig * 2;
        sO[(r0 + g) * 33 + c]     = o[dt][0] * inv0;
        sO[(r0 + g) * 33 + c + 1] = o[dt][1] * inv0;
        sO[(r0 + g + 8) * 33 + c]     = o[dt][2] * inv1;
        sO[(r0 + g + 8) * 33 + c + 1] = o[dt][3] * inv1;
    }
    __syncthreads();

    for (int i = t; i < AQ * DH; i += 256) {
        int d = i >> 7, n = i & 127;
        ob[d * HW + n0 + n] = sO[n * 33 + d];
    }
}

// ---------------------------------------------------------------------------
// Host launcher
// ---------------------------------------------------------------------------
extern "C" void kernel_launch(void* const* d_in, const int* in_sizes, int n_in,
                              void* d_out, int out_size)
{
    const float* x      = (const float*)d_in[0];
    const float* wq     = (const float*)d_in[1];
    const float* bq     = (const float*)d_in[2];
    const float* wk     = (const float*)d_in[3];
    const float* bk     = (const float*)d_in[4];
    const float* wv     = (const float*)d_in[5];
    const float* bv     = (const float*)d_in[6];
    const float* k_dw   = (const float*)d_in[7];
    const float* k_gn1s = (const float*)d_in[8];
    const float* k_gn1b = (const float*)d_in[9];
    const float* k_pw   = (const float*)d_in[10];
    const float* k_gn2s = (const float*)d_in[11];
    const float* k_gn2b = (const float*)d_in[12];
    const float* v_dw   = (const float*)d_in[13];
    const float* v_gn1s = (const float*)d_in[14];
    const float* v_gn1b = (const float*)d_in[15];
    const float* v_pw   = (const float*)d_in[16];
    const float* v_gn2s = (const float*)d_in[17];
    const float* v_gn2b = (const float*)d_in[18];
    float* out = (float*)d_out;

    float* basef = nullptr;
    cudaGetSymbolAddress((void**)&basef, g_scratch);
    __half* base = (__half*)basef;
    __half* q     = base + OFF_Q;
    __half* kfull = base + OFF_KFULL;
    __half* vfull = base + OFF_VFULL;
    __half* kds   = base + OFF_KDS;
    __half* vds   = base + OFF_VDS;
    __half* kbr   = base + OFF_KBR;
    __half* vbr   = base + OFF_VBR;
    __half* xh    = base + OFF_XH;
    __half* wqh   = base + OFF_WQH;
    __half* wkh   = base + OFF_WKH;
    __half* wvh   = base + OFF_WVH;
    __half* kpwh  = base + OFF_KPWH;
    __half* vpwh  = base + OFF_VPWH;

    // 0) prep: weights -> fp16; x -> x^T fp16
    {
        dim3 grid(64, 5);
        wconv_kernel<<<grid, 256>>>(wq, wk, wv, k_pw, v_pw,
                                    wqh, wkh, wvh, kpwh, vpwh);
        dim3 tgrid(HW / 32, CH / 32, BATCH);
        xpose_kernel<<<tgrid, dim3(32, 8)>>>(x, xh);
    }

    // 1) q/k/v pointwise convs fused in one launch (fp16 MMA, 128x128 tiles)
    {
        dim3 grid(HW / 128, 6, BATCH);
        gemm_f16_kernel<<<grid, 256>>>(
            wqh, bq, q,  wkh, bk, kfull,  wvh, bv, vfull,
            xh, xh, xh, HW);
    }

    // 2) fused depthwise s2 + GN1 + SiLU (k & v), outputs [n][k]
    {
        dim3 grid(GROUPS, BATCH, 2);
        dwgn_silu_kernel<<<grid, HWD>>>(kfull, vfull, k_dw, v_dw,
                                        k_gn1s, v_gn1s, k_gn1b, v_gn1b,
                                        kds, vds);
    }

    // 3) pointwise convs (no bias), k & v fused (fp16 MMA)
    {
        dim3 grid(HWD / 128, 4, BATCH);
        gemm_f16_kernel<<<grid, 256>>>(
            kpwh, nullptr, kbr,  vpwh, nullptr, vbr,  kpwh, nullptr, kbr,
            kds, vds, kds, HWD);
    }

    // 4) GN2 + SiLU (k & v, in-place)
    {
        dim3 grid(GROUPS, BATCH, 2);
        gn_silu_kernel<<<grid, HWD>>>(kbr, vbr, k_gn2s, v_gn2s, k_gn2b, v_gn2b);
    }

    // 5) attention -> output (B,C,H,W) fp32
    {
        dim3 grid(HW / AQ, NH, BATCH);
        attn_fp16_kernel<<<grid, 256>>>(q, kbr, vbr, out);
    }
}